// round 3
// baseline (speedup 1.0000x reference)
#include <cuda_runtime.h>
#include <math.h>

// Problem constants
#define Bb   2
#define Mm   2048
#define Dd   2048
#define Hh   16
#define DHh  128
#define DRr  64
#define DQq  192   // concatenated head dim: 128 (C path) + 64 (RoPE path)

__device__ __constant__ float c_scale = 0.07216878364870322f;  // 1/sqrt(192)

// Scratch (static __device__ — no allocations allowed)
__device__ float g_Q[(size_t)Bb * Hh * Mm * DQq];    // (B,H,M,192)
__device__ float g_K[(size_t)Bb * Hh * Mm * DQq];    // (B,H,N,192)
__device__ float g_V[(size_t)Bb * Hh * Mm * DHh];    // (B,H,N,128)
__device__ float g_Ob[(size_t)Bb * Mm * Hh * DHh];   // (B,M,H*128) attn output
__device__ float g_cos[Mm * DRr];
__device__ float g_sin[Mm * DRr];

// ---------------------------------------------------------------------------
// RoPE table: fp64 for angle accuracy at s up to 2048 (tiny kernel)
// ---------------------------------------------------------------------------
__global__ void rope_table_kernel() {
    int s = blockIdx.x;
    int i = threadIdx.x;  // 0..31 : frequency pair index
    double freq = exp(-((double)(2 * i) / 64.0) * log(1000000.0));
    double ang = (double)s * freq;
    float c = (float)cos(ang);
    float sn = (float)sin(ang);
    g_cos[s * 64 + 2 * i] = c;  g_cos[s * 64 + 2 * i + 1] = c;
    g_sin[s * 64 + 2 * i] = sn; g_sin[s * 64 + 2 * i + 1] = sn;
}

// ---------------------------------------------------------------------------
// NT SGEMM: C[r,c] = dot(A[r,:], W[c,:]), K = 2048.
// 128x128x16 tiles, 256 threads, 8x8 micro-tile.
// MODE 0: plain row-major store (out, ldc=2048)
// MODE 1: C-path projection -> (B,H,S,192) at offset 0..127
// MODE 2: R-path projection + RoPE -> (B,H,S,192) at offset 128..191
// MODE 3: V projection -> (B,H,S,128)
// ---------------------------------------------------------------------------
template <int MODE>
__global__ void __launch_bounds__(256, 1)
sgemm_nt(const float* __restrict__ A, const float* __restrict__ W,
         float* __restrict__ out) {
    __shared__ float As[16][128];
    __shared__ float Bs[16][128];
    const int tid = threadIdx.x;
    const int row0 = blockIdx.y * 128;
    const int col0 = blockIdx.x * 128;
    const int lrow = tid >> 2;          // 0..63
    const int lk = (tid & 3) << 2;      // 0,4,8,12
    const float* aP = A + (size_t)(row0 + lrow) * Dd + lk;
    const float* bP = W + (size_t)(col0 + lrow) * Dd + lk;
    const int ty = tid >> 4;
    const int tx = tid & 15;

    float acc[8][8];
#pragma unroll
    for (int i = 0; i < 8; ++i)
#pragma unroll
        for (int j = 0; j < 8; ++j) acc[i][j] = 0.0f;

    for (int k0 = 0; k0 < Dd; k0 += 16) {
        float4 a0 = *(const float4*)(aP);
        float4 a1 = *(const float4*)(aP + (size_t)64 * Dd);
        float4 b0 = *(const float4*)(bP);
        float4 b1 = *(const float4*)(bP + (size_t)64 * Dd);
        __syncthreads();
        As[lk + 0][lrow] = a0.x; As[lk + 1][lrow] = a0.y;
        As[lk + 2][lrow] = a0.z; As[lk + 3][lrow] = a0.w;
        As[lk + 0][lrow + 64] = a1.x; As[lk + 1][lrow + 64] = a1.y;
        As[lk + 2][lrow + 64] = a1.z; As[lk + 3][lrow + 64] = a1.w;
        Bs[lk + 0][lrow] = b0.x; Bs[lk + 1][lrow] = b0.y;
        Bs[lk + 2][lrow] = b0.z; Bs[lk + 3][lrow] = b0.w;
        Bs[lk + 0][lrow + 64] = b1.x; Bs[lk + 1][lrow + 64] = b1.y;
        Bs[lk + 2][lrow + 64] = b1.z; Bs[lk + 3][lrow + 64] = b1.w;
        __syncthreads();
#pragma unroll
        for (int kk = 0; kk < 16; ++kk) {
            float4 aL = *(const float4*)&As[kk][ty * 8];
            float4 aH = *(const float4*)&As[kk][ty * 8 + 4];
            float4 bL = *(const float4*)&Bs[kk][tx * 8];
            float4 bH = *(const float4*)&Bs[kk][tx * 8 + 4];
            float ar[8] = {aL.x, aL.y, aL.z, aL.w, aH.x, aH.y, aH.z, aH.w};
            float br[8] = {bL.x, bL.y, bL.z, bL.w, bH.x, bH.y, bH.z, bH.w};
#pragma unroll
            for (int i = 0; i < 8; ++i)
#pragma unroll
                for (int j = 0; j < 8; ++j)
                    acc[i][j] = fmaf(ar[i], br[j], acc[i][j]);
        }
        aP += 16;
        bP += 16;
    }

    // Epilogue
#pragma unroll
    for (int i = 0; i < 8; ++i) {
        const int r = row0 + ty * 8 + i;
        const int b = r >> 11;        // r / 2048
        const int s = r & 2047;
        if (MODE == 0) {
            float* dst = out + (size_t)r * Dd + col0 + tx * 8;
            *(float4*)(dst) = make_float4(acc[i][0], acc[i][1], acc[i][2], acc[i][3]);
            *(float4*)(dst + 4) = make_float4(acc[i][4], acc[i][5], acc[i][6], acc[i][7]);
        } else if (MODE == 1) {
            const int c = col0 + tx * 8;
            const int h = c >> 7;
            const int jj = c & 127;   // 8 cols stay within one head (8 | 128)
            float* dst = out + (((size_t)(b * Hh + h) * Mm) + s) * DQq + jj;
            *(float4*)(dst) = make_float4(acc[i][0], acc[i][1], acc[i][2], acc[i][3]);
            *(float4*)(dst + 4) = make_float4(acc[i][4], acc[i][5], acc[i][6], acc[i][7]);
        } else if (MODE == 2) {
#pragma unroll
            for (int j = 0; j < 8; j += 2) {
                const int c = col0 + tx * 8 + j;   // even
                const int h = c >> 6;
                const int jr = c & 63;
                const float cs = g_cos[s * 64 + jr];
                const float sn = g_sin[s * 64 + jr];
                const float x0 = acc[i][j];
                const float x1 = acc[i][j + 1];
                float* dst = out + (((size_t)(b * Hh + h) * Mm) + s) * DQq + 128 + jr;
                dst[0] = x0 * cs - x1 * sn;
                dst[1] = x1 * cs + x0 * sn;
            }
        } else {  // MODE 3: V
            const int c = col0 + tx * 8;
            const int h = c >> 7;
            const int jj = c & 127;
            float* dst = out + (((size_t)(b * Hh + h) * Mm) + s) * DHh + jj;
            *(float4*)(dst) = make_float4(acc[i][0], acc[i][1], acc[i][2], acc[i][3]);
            *(float4*)(dst + 4) = make_float4(acc[i][4], acc[i][5], acc[i][6], acc[i][7]);
        }
    }
}

// ---------------------------------------------------------------------------
// Flash attention: per (b,h): softmax(Q K^T * scale) V, d_qk=192, d_v=128.
// CTA: 128 query rows; loop N in 128-key tiles; d processed in 64-wide chunks.
// SMEM: Qt[64][128] + Kt[64][128] + Ps[128][128] + Vs[128][128] = 192 KB.
// ---------------------------------------------------------------------------
__global__ void __launch_bounds__(256, 1)
flash_attn(const float* __restrict__ Q, const float* __restrict__ K,
           const float* __restrict__ V, float* __restrict__ O) {
    extern __shared__ float sm[];
    float* Qt = sm;                   // [k=64][row=128] transposed
    float* Kt = sm + 64 * 128;        // [k=64][col=128] transposed
    float* Ps = sm + 2 * 64 * 128;    // [row=128][key=128]
    float* Vs = Ps + 128 * 128;       // [key=128][d=128]

    const int tid = threadIdx.x;
    const int ty = tid >> 4;
    const int tx = tid & 15;
    const int bh = blockIdx.y;
    const int m0 = blockIdx.x * 128;
    const float* Qbase = Q + ((size_t)bh * Mm + m0) * DQq;
    const float* Kbase = K + (size_t)bh * Mm * DQq;
    const float* Vbase = V + (size_t)bh * Mm * DHh;

    const int lrow = tid >> 2;        // 0..63
    const int lk = (tid & 3) << 2;    // 0,4,8,12

    float o_acc[8][8];
    float mrow[8], lsum[8];
#pragma unroll
    for (int i = 0; i < 8; ++i) {
        mrow[i] = -1e30f;
        lsum[i] = 0.0f;
#pragma unroll
        for (int j = 0; j < 8; ++j) o_acc[i][j] = 0.0f;
    }

    for (int n0 = 0; n0 < Mm; n0 += 128) {
        float s_acc[8][8];
#pragma unroll
        for (int i = 0; i < 8; ++i)
#pragma unroll
            for (int j = 0; j < 8; ++j) s_acc[i][j] = 0.0f;

        // --- S = Q K^T over d in chunks of 64 ---
        for (int dc = 0; dc < DQq; dc += 64) {
            __syncthreads();
#pragma unroll
            for (int p = 0; p < 8; ++p) {
                const int row = lrow + ((p & 1) << 6);  // +0 / +64
                const int kb = lk + ((p >> 1) << 4);    // +0,16,32,48
                float4 q = *(const float4*)(Qbase + (size_t)row * DQq + dc + kb);
                Qt[(kb + 0) * 128 + row] = q.x;
                Qt[(kb + 1) * 128 + row] = q.y;
                Qt[(kb + 2) * 128 + row] = q.z;
                Qt[(kb + 3) * 128 + row] = q.w;
                float4 kv = *(const float4*)(Kbase + (size_t)(n0 + row) * DQq + dc + kb);
                Kt[(kb + 0) * 128 + row] = kv.x;
                Kt[(kb + 1) * 128 + row] = kv.y;
                Kt[(kb + 2) * 128 + row] = kv.z;
                Kt[(kb + 3) * 128 + row] = kv.w;
            }
            __syncthreads();
#pragma unroll 8
            for (int kk = 0; kk < 64; ++kk) {
                float4 aL = *(const float4*)&Qt[kk * 128 + ty * 8];
                float4 aH = *(const float4*)&Qt[kk * 128 + ty * 8 + 4];
                float4 bL = *(const float4*)&Kt[kk * 128 + tx * 8];
                float4 bH = *(const float4*)&Kt[kk * 128 + tx * 8 + 4];
                float ar[8] = {aL.x, aL.y, aL.z, aL.w, aH.x, aH.y, aH.z, aH.w};
                float br[8] = {bL.x, bL.y, bL.z, bL.w, bH.x, bH.y, bH.z, bH.w};
#pragma unroll
                for (int i = 0; i < 8; ++i)
#pragma unroll
                    for (int j = 0; j < 8; ++j)
                        s_acc[i][j] = fmaf(ar[i], br[j], s_acc[i][j]);
            }
        }

        // --- online softmax (per row; 16-lane groups share a row) ---
        const float scale = c_scale;
#pragma unroll
        for (int i = 0; i < 8; ++i) {
            float mx = -1e30f;
#pragma unroll
            for (int j = 0; j < 8; ++j) {
                s_acc[i][j] *= scale;
                mx = fmaxf(mx, s_acc[i][j]);
            }
            mx = fmaxf(mx, __shfl_xor_sync(0xffffffffu, mx, 1));
            mx = fmaxf(mx, __shfl_xor_sync(0xffffffffu, mx, 2));
            mx = fmaxf(mx, __shfl_xor_sync(0xffffffffu, mx, 4));
            mx = fmaxf(mx, __shfl_xor_sync(0xffffffffu, mx, 8));
            const float mnew = fmaxf(mrow[i], mx);
            const float corr = __expf(mrow[i] - mnew);
            mrow[i] = mnew;
            float ps = 0.0f;
#pragma unroll
            for (int j = 0; j < 8; ++j) {
                const float p = __expf(s_acc[i][j] - mnew);
                s_acc[i][j] = p;
                ps += p;
            }
            ps += __shfl_xor_sync(0xffffffffu, ps, 1);
            ps += __shfl_xor_sync(0xffffffffu, ps, 2);
            ps += __shfl_xor_sync(0xffffffffu, ps, 4);
            ps += __shfl_xor_sync(0xffffffffu, ps, 8);
            lsum[i] = lsum[i] * corr + ps;
#pragma unroll
            for (int j = 0; j < 8; ++j) o_acc[i][j] *= corr;
        }

        __syncthreads();
        // --- stage P (row-major, conflict-free float4) and load V tile ---
#pragma unroll
        for (int i = 0; i < 8; ++i) {
            float* pp = &Ps[(ty * 8 + i) * 128 + tx * 8];
            *(float4*)(pp) = make_float4(s_acc[i][0], s_acc[i][1], s_acc[i][2], s_acc[i][3]);
            *(float4*)(pp + 4) = make_float4(s_acc[i][4], s_acc[i][5], s_acc[i][6], s_acc[i][7]);
        }
#pragma unroll
        for (int it = 0; it < 16; ++it) {
            const int flat = tid + it * 256;      // 0..4095
            const int row = flat >> 5;
            const int d4 = (flat & 31) << 2;
            *(float4*)&Vs[row * 128 + d4] =
                *(const float4*)(Vbase + (size_t)(n0 + row) * DHh + d4);
        }
        __syncthreads();

        // --- O += P @ V ---
#pragma unroll 4
        for (int kk = 0; kk < 128; ++kk) {
            float pr[8];
#pragma unroll
            for (int i = 0; i < 8; ++i) pr[i] = Ps[(ty * 8 + i) * 128 + kk];
            float4 vL = *(const float4*)&Vs[kk * 128 + tx * 8];
            float4 vH = *(const float4*)&Vs[kk * 128 + tx * 8 + 4];
            float vr[8] = {vL.x, vL.y, vL.z, vL.w, vH.x, vH.y, vH.z, vH.w};
#pragma unroll
            for (int i = 0; i < 8; ++i)
#pragma unroll
                for (int j = 0; j < 8; ++j)
                    o_acc[i][j] = fmaf(pr[i], vr[j], o_acc[i][j]);
        }
    }

    // --- epilogue: normalize and write (B, M, H*128) ---
    const int b = bh >> 4;
    const int h = bh & 15;
#pragma unroll
    for (int i = 0; i < 8; ++i) {
        const float inv = 1.0f / lsum[i];
        const int m = m0 + ty * 8 + i;
        float* dst = O + ((size_t)(b * Mm + m)) * (Hh * DHh) + h * DHh + tx * 8;
        *(float4*)(dst) = make_float4(o_acc[i][0] * inv, o_acc[i][1] * inv,
                                      o_acc[i][2] * inv, o_acc[i][3] * inv);
        *(float4*)(dst + 4) = make_float4(o_acc[i][4] * inv, o_acc[i][5] * inv,
                                          o_acc[i][6] * inv, o_acc[i][7] * inv);
    }
}

// ---------------------------------------------------------------------------
extern "C" void kernel_launch(void* const* d_in, const int* in_sizes, int n_in,
                              void* d_out, int out_size) {
    (void)in_sizes; (void)n_in; (void)out_size;
    const float* query = (const float*)d_in[0];
    const float* kv    = (const float*)d_in[1];
    const float* W_QC  = (const float*)d_in[2];
    const float* W_KC  = (const float*)d_in[3];
    const float* W_QR  = (const float*)d_in[4];
    const float* W_KR  = (const float*)d_in[5];
    const float* W_V   = (const float*)d_in[6];
    const float* W_O   = (const float*)d_in[7];
    float* out = (float*)d_out;

    float *Qb, *Kb, *Vb, *Ob;
    cudaGetSymbolAddress((void**)&Qb, g_Q);
    cudaGetSymbolAddress((void**)&Kb, g_K);
    cudaGetSymbolAddress((void**)&Vb, g_V);
    cudaGetSymbolAddress((void**)&Ob, g_Ob);

    cudaFuncSetAttribute(flash_attn, cudaFuncAttributeMaxDynamicSharedMemorySize,
                         196608);

    const dim3 blk(256);
    rope_table_kernel<<<Mm, 32>>>();
    sgemm_nt<1><<<dim3(16, 32), blk>>>(query, W_QC, Qb);   // Q_C -> Qb[:,0:128]
    sgemm_nt<2><<<dim3(8, 32), blk>>>(query, W_QR, Qb);    // Q_R+RoPE -> Qb[:,128:192]
    sgemm_nt<1><<<dim3(16, 32), blk>>>(kv, W_KC, Kb);      // K_C
    sgemm_nt<2><<<dim3(8, 32), blk>>>(kv, W_KR, Kb);       // K_R+RoPE
    sgemm_nt<3><<<dim3(16, 32), blk>>>(kv, W_V, Vb);       // V
    flash_attn<<<dim3(16, 32), blk, 196608>>>(Qb, Kb, Vb, Ob);
    sgemm_nt<0><<<dim3(16, 32), blk>>>(Ob, W_O, out);      // final projection
}

// round 8
// speedup vs baseline: 1.9139x; 1.9139x over previous
#include <cuda_runtime.h>
#include <cuda_bf16.h>
#include <math.h>
#include <stdint.h>

// Problem constants
#define Bb   2
#define Mm   2048
#define Dd   2048
#define Hh   16
#define DHh  128
#define DRr  64
#define DQq  192   // concatenated head dim: 128 (C path) + 64 (RoPE path)

__device__ __constant__ float c_scale = 0.07216878364870322f;  // 1/sqrt(192)

// fp32 scratch
__device__ float g_Q[(size_t)Bb * Hh * Mm * DQq];    // (B,H,M,192)
__device__ float g_K[(size_t)Bb * Hh * Mm * DQq];    // (B,H,N,192)
__device__ float g_V[(size_t)Bb * Hh * Mm * DHh];    // (B,H,N,128)
__device__ float g_Ob[(size_t)Bb * Mm * Hh * DHh];   // (B,M,H*128) attn output
__device__ float g_cos[Mm * DRr];
__device__ float g_sin[Mm * DRr];

// bf16 hi/lo split scratch
#define SZ_X  ((size_t)Bb * Mm * Dd)        // 8388608
#define SZ_W2 ((size_t)2048 * 2048)         // 4194304
#define SZ_W1 ((size_t)1024 * 2048)         // 2097152
__device__ __nv_bfloat16 g_qh[SZ_X],  g_ql[SZ_X];
__device__ __nv_bfloat16 g_kvh[SZ_X], g_kvl[SZ_X];
__device__ __nv_bfloat16 g_obh[SZ_X], g_obl[SZ_X];
__device__ __nv_bfloat16 g_wqch[SZ_W2], g_wqcl[SZ_W2];
__device__ __nv_bfloat16 g_wkch[SZ_W2], g_wkcl[SZ_W2];
__device__ __nv_bfloat16 g_wvh[SZ_W2],  g_wvl[SZ_W2];
__device__ __nv_bfloat16 g_woh[SZ_W2],  g_wol[SZ_W2];
__device__ __nv_bfloat16 g_wqrh[SZ_W1], g_wqrl[SZ_W1];
__device__ __nv_bfloat16 g_wkrh[SZ_W1], g_wkrl[SZ_W1];

// ---------------------------------------------------------------------------
// Helpers (generic sm_80/90 features only — target is sm_103 non-'a')
// ---------------------------------------------------------------------------
__device__ __forceinline__ uint32_t smem_u32(const void* p) {
    uint32_t a;
    asm("{ .reg .u64 t; cvta.to.shared.u64 t, %1; cvt.u32.u64 %0, t; }"
        : "=r"(a) : "l"(p));
    return a;
}
__device__ __forceinline__ void cp16(uint32_t s, const void* g) {
    asm volatile("cp.async.cg.shared.global [%0], [%1], 16;" :: "r"(s), "l"(g));
}
#define CP_COMMIT() asm volatile("cp.async.commit_group;" ::: "memory")

__device__ __forceinline__ void ldmx4(uint32_t r[4], uint32_t a) {
    asm volatile("ldmatrix.sync.aligned.m8n8.x4.shared.b16 {%0,%1,%2,%3}, [%4];"
                 : "=r"(r[0]), "=r"(r[1]), "=r"(r[2]), "=r"(r[3]) : "r"(a));
}
__device__ __forceinline__ void mma16816(float c[4], const uint32_t a[4],
                                         uint32_t b0, uint32_t b1) {
    asm volatile(
        "mma.sync.aligned.m16n8k16.row.col.f32.bf16.bf16.f32 "
        "{%0,%1,%2,%3}, {%4,%5,%6,%7}, {%8,%9}, {%0,%1,%2,%3};"
        : "+f"(c[0]), "+f"(c[1]), "+f"(c[2]), "+f"(c[3])
        : "r"(a[0]), "r"(a[1]), "r"(a[2]), "r"(a[3]), "r"(b0), "r"(b1));
}

// ---------------------------------------------------------------------------
// fp32 -> bf16 hi/lo split
// ---------------------------------------------------------------------------
__device__ __forceinline__ uint32_t pack_bf2(__nv_bfloat16 a, __nv_bfloat16 b) {
    return (uint32_t)__bfloat16_as_ushort(a) | ((uint32_t)__bfloat16_as_ushort(b) << 16);
}
__global__ void __launch_bounds__(256)
cvt_split(const float4* __restrict__ src, uint2* __restrict__ hi,
          uint2* __restrict__ lo, int n4) {
    int i = blockIdx.x * 256 + threadIdx.x;
    if (i >= n4) return;
    float4 v = src[i];
    __nv_bfloat16 h0 = __float2bfloat16(v.x), h1 = __float2bfloat16(v.y);
    __nv_bfloat16 h2 = __float2bfloat16(v.z), h3 = __float2bfloat16(v.w);
    __nv_bfloat16 l0 = __float2bfloat16(v.x - __bfloat162float(h0));
    __nv_bfloat16 l1 = __float2bfloat16(v.y - __bfloat162float(h1));
    __nv_bfloat16 l2 = __float2bfloat16(v.z - __bfloat162float(h2));
    __nv_bfloat16 l3 = __float2bfloat16(v.w - __bfloat162float(h3));
    hi[i] = make_uint2(pack_bf2(h0, h1), pack_bf2(h2, h3));
    lo[i] = make_uint2(pack_bf2(l0, l1), pack_bf2(l2, l3));
}

// ---------------------------------------------------------------------------
// RoPE table (fp64 angles)
// ---------------------------------------------------------------------------
__global__ void rope_table_kernel() {
    int s = blockIdx.x;
    int i = threadIdx.x;  // 0..31
    double freq = exp(-((double)(2 * i) / 64.0) * log(1000000.0));
    double ang = (double)s * freq;
    float c = (float)cos(ang);
    float sn = (float)sin(ang);
    g_cos[s * 64 + 2 * i] = c;  g_cos[s * 64 + 2 * i + 1] = c;
    g_sin[s * 64 + 2 * i] = sn; g_sin[s * 64 + 2 * i + 1] = sn;
}

// ---------------------------------------------------------------------------
// HMMA bf16x3 NT GEMM: C[r,c] = dot(A[r,:], B[c,:]), K = 2048.
// CTA tile 128x128, K chunk 64 (bf16, 128B rows, SW128 swizzle), 2 stages.
// 256 threads = 8 warps (2x4), warp tile 64x32, mma.m16n8k16 bf16, fp32 acc.
// A*B ~= Ah*Bh + Ah*Bl + Al*Bh (bf16x3 split).
// MODE 0: plain (ldc=2048)  MODE 1: C-path -> (B,H,S,192)[0:128]
// MODE 2: R-path + RoPE -> (B,H,S,192)[128:192]  MODE 3: V -> (B,H,S,128)
// SMEM/stage: Ah(16K) Al(16K) Bh(16K) Bl(16K) = 64KB; total 128KB.
// ---------------------------------------------------------------------------
__device__ __forceinline__ void load_chunk(uint32_t sb, int tid, int row0, int col0,
        const __nv_bfloat16* Ah, const __nv_bfloat16* Al,
        const __nv_bfloat16* Bh, const __nv_bfloat16* Bl, int c) {
    const int s = c & 1;
    const size_t k0b = (size_t)c * 128;  // 64 bf16 = 128 bytes along K
    const uint32_t base = sb + s * 65536;
    // 1024 16B-chunks per 16KB tile; 256 threads x 4 iters
#pragma unroll
    for (int i = 0; i < 4; ++i) {
        int flat = tid + i * 256;      // 0..1023
        int row = flat >> 3;           // 0..127
        int cb = (flat & 7) << 4;      // 0..112 step 16
        uint32_t so = (uint32_t)(row * 128 + (cb ^ ((row & 7) * 16)));  // SW128
        const size_t ra = ((size_t)(row0 + row) * Dd) * 2 + k0b + cb;
        const size_t rb = ((size_t)(col0 + row) * Dd) * 2 + k0b + cb;
        cp16(base + so,         (const char*)Ah + ra);
        cp16(base + 16384 + so, (const char*)Al + ra);
        cp16(base + 32768 + so, (const char*)Bh + rb);
        cp16(base + 49152 + so, (const char*)Bl + rb);
    }
}

template <int MODE>
__global__ void __launch_bounds__(256, 1)
hmma_gemm(const __nv_bfloat16* __restrict__ Ah, const __nv_bfloat16* __restrict__ Al,
          const __nv_bfloat16* __restrict__ Bh, const __nv_bfloat16* __restrict__ Bl,
          float* __restrict__ out) {
    extern __shared__ __align__(1024) char smem[];
    const uint32_t sb = smem_u32(smem);
    const int tid = threadIdx.x;
    const int wid = tid >> 5, lane = tid & 31;
    const int wm = wid >> 2, wn = wid & 3;       // warp grid 2x4
    const int row0 = blockIdx.y * 128, col0 = blockIdx.x * 128;

    float acc[4][4][4];
#pragma unroll
    for (int mi = 0; mi < 4; ++mi)
#pragma unroll
        for (int ni = 0; ni < 4; ++ni)
#pragma unroll
            for (int k = 0; k < 4; ++k) acc[mi][ni][k] = 0.0f;

    // lane-invariant fragment address pieces
    const int aRow = wm * 64 + (lane & 15);        // + mi*16
    const int aKs  = (lane >> 4) * 16;             // byte sel within k16
    const int bRow = wn * 32 + ((lane >> 4) << 3) + (lane & 7);  // + np*16
    const int bKs  = ((lane >> 3) & 1) * 16;

    load_chunk(sb, tid, row0, col0, Ah, Al, Bh, Bl, 0);
    CP_COMMIT();

    for (int c = 0; c < 32; ++c) {
        const int s = c & 1;
        if (c + 1 < 32) {
            load_chunk(sb, tid, row0, col0, Ah, Al, Bh, Bl, c + 1);
            CP_COMMIT();
            asm volatile("cp.async.wait_group 1;" ::: "memory");
        } else {
            asm volatile("cp.async.wait_group 0;" ::: "memory");
        }
        __syncthreads();
        const uint32_t base = sb + s * 65536;
#pragma unroll
        for (int ks = 0; ks < 4; ++ks) {
            const int kA = ks * 32 + aKs;
            const int kB = ks * 32 + bKs;
            uint32_t ah[4][4], al[4][4];
#pragma unroll
            for (int mi = 0; mi < 4; ++mi) {
                const int r = aRow + mi * 16;
                const uint32_t off = (uint32_t)(r * 128 + (kA ^ ((r & 7) * 16)));
                ldmx4(ah[mi], base + off);
                ldmx4(al[mi], base + 16384 + off);
            }
            uint32_t bh[2][4], bl[2][4];
#pragma unroll
            for (int np = 0; np < 2; ++np) {
                const int r = bRow + np * 16;
                const uint32_t off = (uint32_t)(r * 128 + (kB ^ ((r & 7) * 16)));
                ldmx4(bh[np], base + 32768 + off);
                ldmx4(bl[np], base + 49152 + off);
            }
#pragma unroll
            for (int mi = 0; mi < 4; ++mi)
#pragma unroll
                for (int ni = 0; ni < 4; ++ni) {
                    const uint32_t* ph = &bh[ni >> 1][(ni & 1) * 2];
                    const uint32_t* pl = &bl[ni >> 1][(ni & 1) * 2];
                    mma16816(acc[mi][ni], ah[mi], ph[0], ph[1]);
                    mma16816(acc[mi][ni], ah[mi], pl[0], pl[1]);
                    mma16816(acc[mi][ni], al[mi], ph[0], ph[1]);
                }
        }
        __syncthreads();
    }

    // Epilogue: fragment c0,c1 -> (row, col..col+1); c2,c3 -> (row+8, col..col+1)
#pragma unroll
    for (int mi = 0; mi < 4; ++mi)
#pragma unroll
        for (int ni = 0; ni < 4; ++ni)
#pragma unroll
            for (int h2 = 0; h2 < 2; ++h2) {
                const int row = row0 + wm * 64 + mi * 16 + (lane >> 2) + h2 * 8;
                const int col = col0 + wn * 32 + ni * 8 + (lane & 3) * 2;
                const float v0 = acc[mi][ni][h2 * 2 + 0];
                const float v1 = acc[mi][ni][h2 * 2 + 1];
                const int b = row >> 11;
                const int ss = row & 2047;
                if (MODE == 0) {
                    *(float2*)(out + (size_t)row * Dd + col) = make_float2(v0, v1);
                } else if (MODE == 1) {
                    const int hH = col >> 7, jj = col & 127;
                    float* dst = out + (((size_t)(b * Hh + hH) * Mm) + ss) * DQq + jj;
                    *(float2*)dst = make_float2(v0, v1);
                } else if (MODE == 2) {
                    const int hH = col >> 6, jr = col & 63;  // even
                    const float cv = g_cos[ss * 64 + jr];
                    const float sv = g_sin[ss * 64 + jr];
                    float* dst = out + (((size_t)(b * Hh + hH) * Mm) + ss) * DQq + 128 + jr;
                    *(float2*)dst = make_float2(v0 * cv - v1 * sv, v1 * cv + v0 * sv);
                } else {  // MODE 3: V
                    const int hH = col >> 7, jj = col & 127;
                    float* dst = out + (((size_t)(b * Hh + hH) * Mm) + ss) * DHh + jj;
                    *(float2*)dst = make_float2(v0, v1);
                }
            }
}

// ---------------------------------------------------------------------------
// Flash attention (fp32, unchanged — known correct): softmax(Q K^T * scale) V
// ---------------------------------------------------------------------------
__global__ void __launch_bounds__(256, 1)
flash_attn(const float* __restrict__ Q, const float* __restrict__ K,
           const float* __restrict__ V, float* __restrict__ O) {
    extern __shared__ float sm[];
    float* Qt = sm;
    float* Kt = sm + 64 * 128;
    float* Ps = sm + 2 * 64 * 128;
    float* Vs = Ps + 128 * 128;

    const int tid = threadIdx.x;
    const int ty = tid >> 4;
    const int tx = tid & 15;
    const int bh = blockIdx.y;
    const int m0 = blockIdx.x * 128;
    const float* Qbase = Q + ((size_t)bh * Mm + m0) * DQq;
    const float* Kbase = K + (size_t)bh * Mm * DQq;
    const float* Vbase = V + (size_t)bh * Mm * DHh;

    const int lrow = tid >> 2;
    const int lk = (tid & 3) << 2;

    float o_acc[8][8];
    float mrow[8], lsum[8];
#pragma unroll
    for (int i = 0; i < 8; ++i) {
        mrow[i] = -1e30f;
        lsum[i] = 0.0f;
#pragma unroll
        for (int j = 0; j < 8; ++j) o_acc[i][j] = 0.0f;
    }

    for (int n0 = 0; n0 < Mm; n0 += 128) {
        float s_acc[8][8];
#pragma unroll
        for (int i = 0; i < 8; ++i)
#pragma unroll
            for (int j = 0; j < 8; ++j) s_acc[i][j] = 0.0f;

        for (int dc = 0; dc < DQq; dc += 64) {
            __syncthreads();
#pragma unroll
            for (int p = 0; p < 8; ++p) {
                const int row = lrow + ((p & 1) << 6);
                const int kb = lk + ((p >> 1) << 4);
                float4 q = *(const float4*)(Qbase + (size_t)row * DQq + dc + kb);
                Qt[(kb + 0) * 128 + row] = q.x;
                Qt[(kb + 1) * 128 + row] = q.y;
                Qt[(kb + 2) * 128 + row] = q.z;
                Qt[(kb + 3) * 128 + row] = q.w;
                float4 kv = *(const float4*)(Kbase + (size_t)(n0 + row) * DQq + dc + kb);
                Kt[(kb + 0) * 128 + row] = kv.x;
                Kt[(kb + 1) * 128 + row] = kv.y;
                Kt[(kb + 2) * 128 + row] = kv.z;
                Kt[(kb + 3) * 128 + row] = kv.w;
            }
            __syncthreads();
#pragma unroll 8
            for (int kk = 0; kk < 64; ++kk) {
                float4 aL = *(const float4*)&Qt[kk * 128 + ty * 8];
                float4 aH = *(const float4*)&Qt[kk * 128 + ty * 8 + 4];
                float4 bL = *(const float4*)&Kt[kk * 128 + tx * 8];
                float4 bH = *(const float4*)&Kt[kk * 128 + tx * 8 + 4];
                float ar[8] = {aL.x, aL.y, aL.z, aL.w, aH.x, aH.y, aH.z, aH.w};
                float br[8] = {bL.x, bL.y, bL.z, bL.w, bH.x, bH.y, bH.z, bH.w};
#pragma unroll
                for (int i = 0; i < 8; ++i)
#pragma unroll
                    for (int j = 0; j < 8; ++j)
                        s_acc[i][j] = fmaf(ar[i], br[j], s_acc[i][j]);
            }
        }

        const float scale = c_scale;
#pragma unroll
        for (int i = 0; i < 8; ++i) {
            float mx = -1e30f;
#pragma unroll
            for (int j = 0; j < 8; ++j) {
                s_acc[i][j] *= scale;
                mx = fmaxf(mx, s_acc[i][j]);
            }
            mx = fmaxf(mx, __shfl_xor_sync(0xffffffffu, mx, 1));
            mx = fmaxf(mx, __shfl_xor_sync(0xffffffffu, mx, 2));
            mx = fmaxf(mx, __shfl_xor_sync(0xffffffffu, mx, 4));
            mx = fmaxf(mx, __shfl_xor_sync(0xffffffffu, mx, 8));
            const float mnew = fmaxf(mrow[i], mx);
            const float corr = __expf(mrow[i] - mnew);
            mrow[i] = mnew;
            float ps = 0.0f;
#pragma unroll
            for (int j = 0; j < 8; ++j) {
                const float p = __expf(s_acc[i][j] - mnew);
                s_acc[i][j] = p;
                ps += p;
            }
            ps += __shfl_xor_sync(0xffffffffu, ps, 1);
            ps += __shfl_xor_sync(0xffffffffu, ps, 2);
            ps += __shfl_xor_sync(0xffffffffu, ps, 4);
            ps += __shfl_xor_sync(0xffffffffu, ps, 8);
            lsum[i] = lsum[i] * corr + ps;
#pragma unroll
            for (int j = 0; j < 8; ++j) o_acc[i][j] *= corr;
        }

        __syncthreads();
#pragma unroll
        for (int i = 0; i < 8; ++i) {
            float* pp = &Ps[(ty * 8 + i) * 128 + tx * 8];
            *(float4*)(pp) = make_float4(s_acc[i][0], s_acc[i][1], s_acc[i][2], s_acc[i][3]);
            *(float4*)(pp + 4) = make_float4(s_acc[i][4], s_acc[i][5], s_acc[i][6], s_acc[i][7]);
        }
#pragma unroll
        for (int it = 0; it < 16; ++it) {
            const int flat = tid + it * 256;
            const int row = flat >> 5;
            const int d4 = (flat & 31) << 2;
            *(float4*)&Vs[row * 128 + d4] =
                *(const float4*)(Vbase + (size_t)(n0 + row) * DHh + d4);
        }
        __syncthreads();

#pragma unroll 4
        for (int kk = 0; kk < 128; ++kk) {
            float pr[8];
#pragma unroll
            for (int i = 0; i < 8; ++i) pr[i] = Ps[(ty * 8 + i) * 128 + kk];
            float4 vL = *(const float4*)&Vs[kk * 128 + tx * 8];
            float4 vH = *(const float4*)&Vs[kk * 128 + tx * 8 + 4];
            float vr[8] = {vL.x, vL.y, vL.z, vL.w, vH.x, vH.y, vH.z, vH.w};
#pragma unroll
            for (int i = 0; i < 8; ++i)
#pragma unroll
                for (int j = 0; j < 8; ++j)
                    o_acc[i][j] = fmaf(pr[i], vr[j], o_acc[i][j]);
        }
    }

    const int b = bh >> 4;
    const int h = bh & 15;
#pragma unroll
    for (int i = 0; i < 8; ++i) {
        const float inv = 1.0f / lsum[i];
        const int m = m0 + ty * 8 + i;
        float* dst = O + ((size_t)(b * Mm + m)) * (Hh * DHh) + h * DHh + tx * 8;
        *(float4*)(dst) = make_float4(o_acc[i][0] * inv, o_acc[i][1] * inv,
                                      o_acc[i][2] * inv, o_acc[i][3] * inv);
        *(float4*)(dst + 4) = make_float4(o_acc[i][4] * inv, o_acc[i][5] * inv,
                                          o_acc[i][6] * inv, o_acc[i][7] * inv);
    }
}

// ---------------------------------------------------------------------------
extern "C" void kernel_launch(void* const* d_in, const int* in_sizes, int n_in,
                              void* d_out, int out_size) {
    (void)in_sizes; (void)n_in; (void)out_size;
    const float* query = (const float*)d_in[0];
    const float* kv    = (const float*)d_in[1];
    const float* W_QC  = (const float*)d_in[2];
    const float* W_KC  = (const float*)d_in[3];
    const float* W_QR  = (const float*)d_in[4];
    const float* W_KR  = (const float*)d_in[5];
    const float* W_V   = (const float*)d_in[6];
    const float* W_O   = (const float*)d_in[7];
    float* out = (float*)d_out;

    float *Qb, *Kb, *Vb, *Ob;
    cudaGetSymbolAddress((void**)&Qb, g_Q);
    cudaGetSymbolAddress((void**)&Kb, g_K);
    cudaGetSymbolAddress((void**)&Vb, g_V);
    cudaGetSymbolAddress((void**)&Ob, g_Ob);
    __nv_bfloat16 *qh, *ql, *kvh, *kvl, *obh, *obl;
    __nv_bfloat16 *wqch, *wqcl, *wkch, *wkcl, *wvh, *wvl, *woh, *wol;
    __nv_bfloat16 *wqrh, *wqrl, *wkrh, *wkrl;
    cudaGetSymbolAddress((void**)&qh, g_qh);   cudaGetSymbolAddress((void**)&ql, g_ql);
    cudaGetSymbolAddress((void**)&kvh, g_kvh); cudaGetSymbolAddress((void**)&kvl, g_kvl);
    cudaGetSymbolAddress((void**)&obh, g_obh); cudaGetSymbolAddress((void**)&obl, g_obl);
    cudaGetSymbolAddress((void**)&wqch, g_wqch); cudaGetSymbolAddress((void**)&wqcl, g_wqcl);
    cudaGetSymbolAddress((void**)&wkch, g_wkch); cudaGetSymbolAddress((void**)&wkcl, g_wkcl);
    cudaGetSymbolAddress((void**)&wvh, g_wvh);   cudaGetSymbolAddress((void**)&wvl, g_wvl);
    cudaGetSymbolAddress((void**)&woh, g_woh);   cudaGetSymbolAddress((void**)&wol, g_wol);
    cudaGetSymbolAddress((void**)&wqrh, g_wqrh); cudaGetSymbolAddress((void**)&wqrl, g_wqrl);
    cudaGetSymbolAddress((void**)&wkrh, g_wkrh); cudaGetSymbolAddress((void**)&wkrl, g_wkrl);

    const int GEMM_SMEM = 131072;  // 2 stages x 64KB
    cudaFuncSetAttribute(hmma_gemm<0>, cudaFuncAttributeMaxDynamicSharedMemorySize, GEMM_SMEM);
    cudaFuncSetAttribute(hmma_gemm<1>, cudaFuncAttributeMaxDynamicSharedMemorySize, GEMM_SMEM);
    cudaFuncSetAttribute(hmma_gemm<2>, cudaFuncAttributeMaxDynamicSharedMemorySize, GEMM_SMEM);
    cudaFuncSetAttribute(hmma_gemm<3>, cudaFuncAttributeMaxDynamicSharedMemorySize, GEMM_SMEM);
    cudaFuncSetAttribute(flash_attn, cudaFuncAttributeMaxDynamicSharedMemorySize, 196608);

    rope_table_kernel<<<Mm, 32>>>();
    // fp32 -> bf16 hi/lo splits
    cvt_split<<<(int)(SZ_X / 1024), 256>>>((const float4*)query, (uint2*)qh, (uint2*)ql, (int)(SZ_X / 4));
    cvt_split<<<(int)(SZ_X / 1024), 256>>>((const float4*)kv, (uint2*)kvh, (uint2*)kvl, (int)(SZ_X / 4));
    cvt_split<<<(int)(SZ_W2 / 1024), 256>>>((const float4*)W_QC, (uint2*)wqch, (uint2*)wqcl, (int)(SZ_W2 / 4));
    cvt_split<<<(int)(SZ_W2 / 1024), 256>>>((const float4*)W_KC, (uint2*)wkch, (uint2*)wkcl, (int)(SZ_W2 / 4));
    cvt_split<<<(int)(SZ_W1 / 1024), 256>>>((const float4*)W_QR, (uint2*)wqrh, (uint2*)wqrl, (int)(SZ_W1 / 4));
    cvt_split<<<(int)(SZ_W1 / 1024), 256>>>((const float4*)W_KR, (uint2*)wkrh, (uint2*)wkrl, (int)(SZ_W1 / 4));
    cvt_split<<<(int)(SZ_W2 / 1024), 256>>>((const float4*)W_V, (uint2*)wvh, (uint2*)wvl, (int)(SZ_W2 / 4));
    cvt_split<<<(int)(SZ_W2 / 1024), 256>>>((const float4*)W_O, (uint2*)woh, (uint2*)wol, (int)(SZ_W2 / 4));

    // HMMA bf16x3 projections
    hmma_gemm<1><<<dim3(16, 32), 256, GEMM_SMEM>>>(qh, ql, wqch, wqcl, Qb);
    hmma_gemm<2><<<dim3(8, 32), 256, GEMM_SMEM>>>(qh, ql, wqrh, wqrl, Qb);
    hmma_gemm<1><<<dim3(16, 32), 256, GEMM_SMEM>>>(kvh, kvl, wkch, wkcl, Kb);
    hmma_gemm<2><<<dim3(8, 32), 256, GEMM_SMEM>>>(kvh, kvl, wkrh, wkrl, Kb);
    hmma_gemm<3><<<dim3(16, 32), 256, GEMM_SMEM>>>(kvh, kvl, wvh, wvl, Vb);

    flash_attn<<<dim3(16, 32), 256, 196608>>>(Qb, Kb, Vb, Ob);

    cvt_split<<<(int)(SZ_X / 1024), 256>>>((const float4*)Ob, (uint2*)obh, (uint2*)obl, (int)(SZ_X / 4));
    hmma_gemm<0><<<dim3(16, 32), 256, GEMM_SMEM>>>(obh, obl, woh, wol, out);
}

// round 10
// speedup vs baseline: 2.5219x; 1.3177x over previous
#include <cuda_runtime.h>
#include <cuda_bf16.h>
#include <math.h>
#include <stdint.h>

// Problem constants
#define Bb   2
#define Mm   2048
#define Dd   2048
#define Hh   16
#define DHh  128
#define DRr  64
#define DQq  192   // concatenated head dim: 128 (C path) + 64 (RoPE path)

__device__ __constant__ float c_scale = 0.07216878364870322f;  // 1/sqrt(192)

__device__ float g_cos[Mm * DRr];
__device__ float g_sin[Mm * DRr];

// bf16 hi/lo split scratch
#define SZ_X  ((size_t)Bb * Mm * Dd)        // 8388608
#define SZ_W2 ((size_t)2048 * 2048)
#define SZ_W1 ((size_t)1024 * 2048)
#define SZ_QK ((size_t)Bb * Hh * Mm * DQq)  // 12582912
#define SZ_V  ((size_t)Bb * Hh * DHh * Mm)  // 8388608
__device__ __nv_bfloat16 g_qh[SZ_X],  g_ql[SZ_X];
__device__ __nv_bfloat16 g_kvh[SZ_X], g_kvl[SZ_X];
__device__ __nv_bfloat16 g_obh[SZ_X], g_obl[SZ_X];
__device__ __nv_bfloat16 g_wqch[SZ_W2], g_wqcl[SZ_W2];
__device__ __nv_bfloat16 g_wkch[SZ_W2], g_wkcl[SZ_W2];
__device__ __nv_bfloat16 g_wvh[SZ_W2],  g_wvl[SZ_W2];
__device__ __nv_bfloat16 g_woh[SZ_W2],  g_wol[SZ_W2];
__device__ __nv_bfloat16 g_wqrh[SZ_W1], g_wqrl[SZ_W1];
__device__ __nv_bfloat16 g_wkrh[SZ_W1], g_wkrl[SZ_W1];
// attention operands (bf16 hi/lo, written by projection epilogues)
__device__ __nv_bfloat16 g_Qh[SZ_QK], g_Ql[SZ_QK];   // (B,H,M,192)
__device__ __nv_bfloat16 g_Kh[SZ_QK], g_Kl[SZ_QK];   // (B,H,N,192)
__device__ __nv_bfloat16 g_Vth[SZ_V], g_Vtl[SZ_V];   // (B,H,128d,2048s) transposed

// ---------------------------------------------------------------------------
// Helpers (generic sm_80/90 features only — target is sm_103 non-'a')
// ---------------------------------------------------------------------------
__device__ __forceinline__ uint32_t smem_u32(const void* p) {
    uint32_t a;
    asm("{ .reg .u64 t; cvta.to.shared.u64 t, %1; cvt.u32.u64 %0, t; }"
        : "=r"(a) : "l"(p));
    return a;
}
__device__ __forceinline__ void cp16(uint32_t s, const void* g) {
    asm volatile("cp.async.cg.shared.global [%0], [%1], 16;" :: "r"(s), "l"(g));
}
#define CP_COMMIT() asm volatile("cp.async.commit_group;" ::: "memory")
#define CP_WAIT0()  asm volatile("cp.async.wait_group 0;" ::: "memory")

__device__ __forceinline__ void ldmx4(uint32_t r[4], uint32_t a) {
    asm volatile("ldmatrix.sync.aligned.m8n8.x4.shared.b16 {%0,%1,%2,%3}, [%4];"
                 : "=r"(r[0]), "=r"(r[1]), "=r"(r[2]), "=r"(r[3]) : "r"(a));
}
__device__ __forceinline__ void mma16816(float c[4], const uint32_t a[4],
                                         uint32_t b0, uint32_t b1) {
    asm volatile(
        "mma.sync.aligned.m16n8k16.row.col.f32.bf16.bf16.f32 "
        "{%0,%1,%2,%3}, {%4,%5,%6,%7}, {%8,%9}, {%0,%1,%2,%3};"
        : "+f"(c[0]), "+f"(c[1]), "+f"(c[2]), "+f"(c[3])
        : "r"(a[0]), "r"(a[1]), "r"(a[2]), "r"(a[3]), "r"(b0), "r"(b1));
}
__device__ __forceinline__ uint32_t pack_bf2(__nv_bfloat16 a, __nv_bfloat16 b) {
    return (uint32_t)__bfloat16_as_ushort(a) | ((uint32_t)__bfloat16_as_ushort(b) << 16);
}
__device__ __forceinline__ uint32_t pack_hi(float x, float y) {
    return pack_bf2(__float2bfloat16(x), __float2bfloat16(y));
}
__device__ __forceinline__ uint32_t pack_lo(float x, float y) {
    __nv_bfloat16 hx = __float2bfloat16(x), hy = __float2bfloat16(y);
    return pack_bf2(__float2bfloat16(x - __bfloat162float(hx)),
                    __float2bfloat16(y - __bfloat162float(hy)));
}

// ---------------------------------------------------------------------------
// fp32 -> bf16 hi/lo split
// ---------------------------------------------------------------------------
__global__ void __launch_bounds__(256)
cvt_split(const float4* __restrict__ src, uint2* __restrict__ hi,
          uint2* __restrict__ lo, int n4) {
    int i = blockIdx.x * 256 + threadIdx.x;
    if (i >= n4) return;
    float4 v = src[i];
    hi[i] = make_uint2(pack_hi(v.x, v.y), pack_hi(v.z, v.w));
    lo[i] = make_uint2(pack_lo(v.x, v.y), pack_lo(v.z, v.w));
}

// ---------------------------------------------------------------------------
// RoPE table (fp64 angles)
// ---------------------------------------------------------------------------
__global__ void rope_table_kernel() {
    int s = blockIdx.x;
    int i = threadIdx.x;  // 0..31
    double freq = exp(-((double)(2 * i) / 64.0) * log(1000000.0));
    double ang = (double)s * freq;
    float c = (float)cos(ang);
    float sn = (float)sin(ang);
    g_cos[s * 64 + 2 * i] = c;  g_cos[s * 64 + 2 * i + 1] = c;
    g_sin[s * 64 + 2 * i] = sn; g_sin[s * 64 + 2 * i + 1] = sn;
}

// ---------------------------------------------------------------------------
// HMMA bf16x3 NT GEMM (pipeline-race-fixed, bf16 hi/lo epilogues)
// MODE 0: fp32 plain (ldc=2048)   MODE 1: -> Q/K hi+lo (B,H,S,192)[0:128]
// MODE 2: RoPE -> (B,H,S,192)[128:192]   MODE 3: V -> transposed (B,H,128,2048)
// ---------------------------------------------------------------------------
__device__ __forceinline__ void load_chunk(uint32_t sb, int tid, int row0, int col0,
        const __nv_bfloat16* Ah, const __nv_bfloat16* Al,
        const __nv_bfloat16* Bh, const __nv_bfloat16* Bl, int c) {
    const int s = c & 1;
    const size_t k0b = (size_t)c * 128;
    const uint32_t base = sb + s * 65536;
#pragma unroll
    for (int i = 0; i < 4; ++i) {
        int flat = tid + i * 256;
        int row = flat >> 3;
        int cb = (flat & 7) << 4;
        uint32_t so = (uint32_t)(row * 128 + (cb ^ ((row & 7) * 16)));
        const size_t ra = ((size_t)(row0 + row) * Dd) * 2 + k0b + cb;
        const size_t rb = ((size_t)(col0 + row) * Dd) * 2 + k0b + cb;
        cp16(base + so,         (const char*)Ah + ra);
        cp16(base + 16384 + so, (const char*)Al + ra);
        cp16(base + 32768 + so, (const char*)Bh + rb);
        cp16(base + 49152 + so, (const char*)Bl + rb);
    }
}

template <int MODE>
__global__ void __launch_bounds__(256, 1)
hmma_gemm(const __nv_bfloat16* __restrict__ Ah, const __nv_bfloat16* __restrict__ Al,
          const __nv_bfloat16* __restrict__ Bh, const __nv_bfloat16* __restrict__ Bl,
          float* __restrict__ outf,
          __nv_bfloat16* __restrict__ oh, __nv_bfloat16* __restrict__ ol) {
    extern __shared__ __align__(1024) char smem[];
    const uint32_t sb = smem_u32(smem);
    const int tid = threadIdx.x;
    const int wid = tid >> 5, lane = tid & 31;
    const int wm = wid >> 2, wn = wid & 3;
    const int row0 = blockIdx.y * 128, col0 = blockIdx.x * 128;

    float acc[4][4][4];
#pragma unroll
    for (int mi = 0; mi < 4; ++mi)
#pragma unroll
        for (int ni = 0; ni < 4; ++ni)
#pragma unroll
            for (int k = 0; k < 4; ++k) acc[mi][ni][k] = 0.0f;

    const int aRow = wm * 64 + (lane & 15);
    const int aKs  = (lane >> 4) * 16;
    const int bRow = wn * 32 + ((lane >> 4) << 3) + (lane & 7);
    const int bKs  = ((lane >> 3) & 1) * 16;

    load_chunk(sb, tid, row0, col0, Ah, Al, Bh, Bl, 0);
    CP_COMMIT();

    for (int c = 0; c < 32; ++c) {
        CP_WAIT0();
        __syncthreads();
        if (c + 1 < 32) {
            load_chunk(sb, tid, row0, col0, Ah, Al, Bh, Bl, c + 1);
            CP_COMMIT();
        }
        const uint32_t base = sb + (c & 1) * 65536;
#pragma unroll
        for (int ks = 0; ks < 4; ++ks) {
            const int kA = ks * 32 + aKs;
            const int kB = ks * 32 + bKs;
            uint32_t ah[4][4], al[4][4];
#pragma unroll
            for (int mi = 0; mi < 4; ++mi) {
                const int r = aRow + mi * 16;
                const uint32_t off = (uint32_t)(r * 128 + (kA ^ ((r & 7) * 16)));
                ldmx4(ah[mi], base + off);
                ldmx4(al[mi], base + 16384 + off);
            }
            uint32_t bh[2][4], bl[2][4];
#pragma unroll
            for (int np = 0; np < 2; ++np) {
                const int r = bRow + np * 16;
                const uint32_t off = (uint32_t)(r * 128 + (kB ^ ((r & 7) * 16)));
                ldmx4(bh[np], base + 32768 + off);
                ldmx4(bl[np], base + 49152 + off);
            }
#pragma unroll
            for (int mi = 0; mi < 4; ++mi)
#pragma unroll
                for (int ni = 0; ni < 4; ++ni) {
                    const uint32_t* ph = &bh[ni >> 1][(ni & 1) * 2];
                    const uint32_t* pl = &bl[ni >> 1][(ni & 1) * 2];
                    mma16816(acc[mi][ni], ah[mi], ph[0], ph[1]);
                    mma16816(acc[mi][ni], ah[mi], pl[0], pl[1]);
                    mma16816(acc[mi][ni], al[mi], ph[0], ph[1]);
                }
        }
        __syncthreads();
    }

#pragma unroll
    for (int mi = 0; mi < 4; ++mi)
#pragma unroll
        for (int ni = 0; ni < 4; ++ni)
#pragma unroll
            for (int h2 = 0; h2 < 2; ++h2) {
                const int row = row0 + wm * 64 + mi * 16 + (lane >> 2) + h2 * 8;
                const int col = col0 + wn * 32 + ni * 8 + (lane & 3) * 2;
                const float v0 = acc[mi][ni][h2 * 2 + 0];
                const float v1 = acc[mi][ni][h2 * 2 + 1];
                const int b = row >> 11;
                const int ss = row & 2047;
                if (MODE == 0) {
                    *(float2*)(outf + (size_t)row * Dd + col) = make_float2(v0, v1);
                } else if (MODE == 1) {
                    const int hH = col >> 7, jj = col & 127;
                    const size_t idx = (((size_t)(b * Hh + hH) * Mm) + ss) * DQq + jj;
                    *(uint32_t*)(oh + idx) = pack_hi(v0, v1);
                    *(uint32_t*)(ol + idx) = pack_lo(v0, v1);
                } else if (MODE == 2) {
                    const int hH = col >> 6, jr = col & 63;
                    const float cv = g_cos[ss * 64 + jr];
                    const float sv = g_sin[ss * 64 + jr];
                    const float y0 = v0 * cv - v1 * sv;
                    const float y1 = v1 * cv + v0 * sv;
                    const size_t idx = (((size_t)(b * Hh + hH) * Mm) + ss) * DQq + 128 + jr;
                    *(uint32_t*)(oh + idx) = pack_hi(y0, y1);
                    *(uint32_t*)(ol + idx) = pack_lo(y0, y1);
                } else {  // MODE 3: V transposed (B,H,128,2048)
                    const int hH = col >> 7, jj = col & 127;
                    const size_t idx = (((size_t)(b * Hh + hH) * DHh) + jj) * Mm + ss;
                    __nv_bfloat16 h0 = __float2bfloat16(v0);
                    __nv_bfloat16 h1 = __float2bfloat16(v1);
                    oh[idx] = h0;
                    ol[idx] = __float2bfloat16(v0 - __bfloat162float(h0));
                    oh[idx + Mm] = h1;
                    ol[idx + Mm] = __float2bfloat16(v1 - __bfloat162float(h1));
                }
            }
}

// ---------------------------------------------------------------------------
// Flash attention, HMMA bf16x3. Per (b,h): 128 q-rows/CTA, 8 warps (16 rows ea).
// SMEM: Qh/Ql resident 3x[128x64] (96KB) + K 2-stage [128x64]x2 (64KB)
//       + V^T [128x128] hi/lo (64KB) = 224KB.
// ---------------------------------------------------------------------------
#define SB_QL   49152
#define SB_K    98304
#define SB_VTH  163840
#define SB_VTL  196608
#define FA_SMEM 229376

__device__ __forceinline__ void ld_tile128(uint32_t dst, int tid,
        const __nv_bfloat16* src, int lds) {
#pragma unroll
    for (int i = 0; i < 4; ++i) {
        int flat = tid + i * 256;
        int row = flat >> 3;
        int cb = (flat & 7) << 4;
        uint32_t so = (uint32_t)(row * 128 + (cb ^ ((row & 7) * 16)));
        cp16(dst + so, (const char*)src + (size_t)row * lds * 2 + cb);
    }
}
__device__ __forceinline__ void ld_tile256(uint32_t dst, int tid,
        const __nv_bfloat16* src, int lds) {
#pragma unroll
    for (int i = 0; i < 8; ++i) {
        int flat = tid + i * 256;
        int row = flat >> 4;
        int cb = (flat & 15) << 4;
        uint32_t so = (uint32_t)(row * 256 + (cb ^ ((row & 7) * 16)));
        cp16(dst + so, (const char*)src + (size_t)row * lds * 2 + cb);
    }
}

__global__ void __launch_bounds__(256, 1)
flash_hmma(const __nv_bfloat16* __restrict__ Qh, const __nv_bfloat16* __restrict__ Ql,
           const __nv_bfloat16* __restrict__ Kh, const __nv_bfloat16* __restrict__ Kl,
           const __nv_bfloat16* __restrict__ Vth, const __nv_bfloat16* __restrict__ Vtl,
           __nv_bfloat16* __restrict__ Oh, __nv_bfloat16* __restrict__ Ol) {
    extern __shared__ __align__(1024) char smem[];
    const uint32_t sb = smem_u32(smem);
    const int tid = threadIdx.x;
    const int wid = tid >> 5, lane = tid & 31;
    const int bh = blockIdx.y;
    const int m0 = blockIdx.x * 128;

    const __nv_bfloat16* Qhb = Qh + ((size_t)bh * Mm + m0) * DQq;
    const __nv_bfloat16* Qlb = Ql + ((size_t)bh * Mm + m0) * DQq;
    const __nv_bfloat16* Khb = Kh + (size_t)bh * Mm * DQq;
    const __nv_bfloat16* Klb = Kl + (size_t)bh * Mm * DQq;
    const __nv_bfloat16* Vhb = Vth + (size_t)bh * DHh * Mm;
    const __nv_bfloat16* Vlb = Vtl + (size_t)bh * DHh * Mm;

    float o_acc[16][4];
#pragma unroll
    for (int ni = 0; ni < 16; ++ni)
#pragma unroll
        for (int k = 0; k < 4; ++k) o_acc[ni][k] = 0.0f;
    float mrow0 = -1e30f, mrow1 = -1e30f, lsum0 = 0.0f, lsum1 = 0.0f;

    // prologue: resident Q (3 chunks hi+lo) + K chunk 0
#pragma unroll
    for (int dc = 0; dc < 3; ++dc) {
        ld_tile128(sb + dc * 16384, tid, Qhb + dc * 64, DQq);
        ld_tile128(sb + SB_QL + dc * 16384, tid, Qlb + dc * 64, DQq);
    }
    ld_tile128(sb + SB_K, tid, Khb, DQq);
    ld_tile128(sb + SB_K + 16384, tid, Klb, DQq);
    CP_COMMIT();

    int t = 0;
#pragma unroll 1
    for (int n0i = 0; n0i < 16; ++n0i) {
        float sacc[16][4];
#pragma unroll
        for (int ni = 0; ni < 16; ++ni)
#pragma unroll
            for (int k = 0; k < 4; ++k) sacc[ni][k] = 0.0f;

#pragma unroll 1
        for (int dc = 0; dc < 3; ++dc) {
            CP_WAIT0();
            __syncthreads();
            // issue chunk t+1 (+ V tile when (t+1)%3==2)
            if (t + 1 < 48) {
                const int nn = (t + 1) / 3, ndc = (t + 1) % 3;
                const uint32_t kst = SB_K + (uint32_t)((t + 1) & 1) * 32768;
                ld_tile128(sb + kst, tid, Khb + (size_t)(nn * 128) * DQq + ndc * 64, DQq);
                ld_tile128(sb + kst + 16384, tid, Klb + (size_t)(nn * 128) * DQq + ndc * 64, DQq);
                if (ndc == 2) {
                    ld_tile256(sb + SB_VTH, tid, Vhb + nn * 128, Mm);
                    ld_tile256(sb + SB_VTL, tid, Vlb + nn * 128, Mm);
                }
                CP_COMMIT();
            }
            // S += Q_chunk @ K_chunk^T  (bf16x3)
            const uint32_t kbase = sb + SB_K + (uint32_t)(t & 1) * 32768;
            const uint32_t qbase = sb + (uint32_t)dc * 16384;
            const uint32_t qlbase = sb + SB_QL + (uint32_t)dc * 16384;
#pragma unroll
            for (int ks = 0; ks < 4; ++ks) {
                const int rA = wid * 16 + (lane & 15);
                const uint32_t offA = (uint32_t)(rA * 128 +
                    ((ks * 32 + (lane >> 4) * 16) ^ ((rA & 7) * 16)));
                uint32_t ah[4], al2[4];
                ldmx4(ah, qbase + offA);
                ldmx4(al2, qlbase + offA);
#pragma unroll
                for (int np = 0; np < 8; ++np) {
                    const int rB = np * 16 + ((lane >> 4) << 3) + (lane & 7);
                    const uint32_t offB = (uint32_t)(rB * 128 +
                        ((ks * 32 + ((lane >> 3) & 1) * 16) ^ ((rB & 7) * 16)));
                    uint32_t bh4[4], bl4[4];
                    ldmx4(bh4, kbase + offB);
                    ldmx4(bl4, kbase + 16384 + offB);
                    mma16816(sacc[np * 2], ah, bh4[0], bh4[1]);
                    mma16816(sacc[np * 2], ah, bl4[0], bl4[1]);
                    mma16816(sacc[np * 2], al2, bh4[0], bh4[1]);
                    mma16816(sacc[np * 2 + 1], ah, bh4[2], bh4[3]);
                    mma16816(sacc[np * 2 + 1], ah, bl4[2], bl4[3]);
                    mma16816(sacc[np * 2 + 1], al2, bh4[2], bh4[3]);
                }
            }
            ++t;
        }

        // --- online softmax (rows: lane>>2 and lane>>2+8 within warp tile) ---
        const float scale = c_scale;
        float mx0 = -1e30f, mx1 = -1e30f;
#pragma unroll
        for (int ni = 0; ni < 16; ++ni) {
            sacc[ni][0] *= scale; sacc[ni][1] *= scale;
            sacc[ni][2] *= scale; sacc[ni][3] *= scale;
            mx0 = fmaxf(mx0, fmaxf(sacc[ni][0], sacc[ni][1]));
            mx1 = fmaxf(mx1, fmaxf(sacc[ni][2], sacc[ni][3]));
        }
        mx0 = fmaxf(mx0, __shfl_xor_sync(0xffffffffu, mx0, 1));
        mx0 = fmaxf(mx0, __shfl_xor_sync(0xffffffffu, mx0, 2));
        mx1 = fmaxf(mx1, __shfl_xor_sync(0xffffffffu, mx1, 1));
        mx1 = fmaxf(mx1, __shfl_xor_sync(0xffffffffu, mx1, 2));
        const float mn0 = fmaxf(mrow0, mx0), mn1 = fmaxf(mrow1, mx1);
        const float cr0 = __expf(mrow0 - mn0), cr1 = __expf(mrow1 - mn1);
        mrow0 = mn0; mrow1 = mn1;
        float ps0 = 0.0f, ps1 = 0.0f;
#pragma unroll
        for (int ni = 0; ni < 16; ++ni) {
            sacc[ni][0] = __expf(sacc[ni][0] - mn0);
            sacc[ni][1] = __expf(sacc[ni][1] - mn0);
            sacc[ni][2] = __expf(sacc[ni][2] - mn1);
            sacc[ni][3] = __expf(sacc[ni][3] - mn1);
            ps0 += sacc[ni][0] + sacc[ni][1];
            ps1 += sacc[ni][2] + sacc[ni][3];
        }
        ps0 += __shfl_xor_sync(0xffffffffu, ps0, 1);
        ps0 += __shfl_xor_sync(0xffffffffu, ps0, 2);
        ps1 += __shfl_xor_sync(0xffffffffu, ps1, 1);
        ps1 += __shfl_xor_sync(0xffffffffu, ps1, 2);
        lsum0 = lsum0 * cr0 + ps0;
        lsum1 = lsum1 * cr1 + ps1;
#pragma unroll
        for (int ni = 0; ni < 16; ++ni) {
            o_acc[ni][0] *= cr0; o_acc[ni][1] *= cr0;
            o_acc[ni][2] *= cr1; o_acc[ni][3] *= cr1;
        }

        // --- O += P @ V  (P frags direct from S accumulators; bf16x3) ---
#pragma unroll 1
        for (int ki = 0; ki < 8; ++ki) {
            uint32_t aph[4], apl[4];
#pragma unroll
            for (int half = 0; half < 2; ++half) {
                const float* p = sacc[2 * ki + half];
                aph[half * 2 + 0] = pack_hi(p[0], p[1]);
                aph[half * 2 + 1] = pack_hi(p[2], p[3]);
                apl[half * 2 + 0] = pack_lo(p[0], p[1]);
                apl[half * 2 + 1] = pack_lo(p[2], p[3]);
            }
#pragma unroll
            for (int np = 0; np < 8; ++np) {
                const int rB = np * 16 + ((lane >> 4) << 3) + (lane & 7);
                const uint32_t offB = (uint32_t)(rB * 256 +
                    ((ki * 32 + ((lane >> 3) & 1) * 16) ^ ((rB & 7) * 16)));
                uint32_t vh4[4], vl4[4];
                ldmx4(vh4, sb + SB_VTH + offB);
                ldmx4(vl4, sb + SB_VTL + offB);
                mma16816(o_acc[np * 2], aph, vh4[0], vh4[1]);
                mma16816(o_acc[np * 2], aph, vl4[0], vl4[1]);
                mma16816(o_acc[np * 2], apl, vh4[0], vh4[1]);
                mma16816(o_acc[np * 2 + 1], aph, vh4[2], vh4[3]);
                mma16816(o_acc[np * 2 + 1], aph, vl4[2], vl4[3]);
                mma16816(o_acc[np * 2 + 1], apl, vh4[2], vh4[3]);
            }
        }
    }

    // --- epilogue: normalize, split hi/lo, write (B,M,2048) ---
    const float inv0 = 1.0f / lsum0, inv1 = 1.0f / lsum1;
    const int b = bh >> 4, h = bh & 15;
    const int g = lane >> 2, t2 = lane & 3;
    const int mrow = m0 + wid * 16 + g;
#pragma unroll
    for (int ni = 0; ni < 16; ++ni) {
        const int col = h * DHh + ni * 8 + t2 * 2;
        const float y0 = o_acc[ni][0] * inv0, y1 = o_acc[ni][1] * inv0;
        const float z0 = o_acc[ni][2] * inv1, z1 = o_acc[ni][3] * inv1;
        const size_t i0 = ((size_t)(b * Mm + mrow)) * Dd + col;
        const size_t i1 = ((size_t)(b * Mm + mrow + 8)) * Dd + col;
        *(uint32_t*)(Oh + i0) = pack_hi(y0, y1);
        *(uint32_t*)(Ol + i0) = pack_lo(y0, y1);
        *(uint32_t*)(Oh + i1) = pack_hi(z0, z1);
        *(uint32_t*)(Ol + i1) = pack_lo(z0, z1);
    }
}

// ---------------------------------------------------------------------------
extern "C" void kernel_launch(void* const* d_in, const int* in_sizes, int n_in,
                              void* d_out, int out_size) {
    (void)in_sizes; (void)n_in; (void)out_size;
    const float* query = (const float*)d_in[0];
    const float* kv    = (const float*)d_in[1];
    const float* W_QC  = (const float*)d_in[2];
    const float* W_KC  = (const float*)d_in[3];
    const float* W_QR  = (const float*)d_in[4];
    const float* W_KR  = (const float*)d_in[5];
    const float* W_V   = (const float*)d_in[6];
    const float* W_O   = (const float*)d_in[7];
    float* out = (float*)d_out;

    __nv_bfloat16 *qh, *ql, *kvh, *kvl, *obh, *obl;
    __nv_bfloat16 *wqch, *wqcl, *wkch, *wkcl, *wvh, *wvl, *woh, *wol;
    __nv_bfloat16 *wqrh, *wqrl, *wkrh, *wkrl;
    __nv_bfloat16 *Qhp, *Qlp, *Khp, *Klp, *Vthp, *Vtlp;
    cudaGetSymbolAddress((void**)&qh, g_qh);   cudaGetSymbolAddress((void**)&ql, g_ql);
    cudaGetSymbolAddress((void**)&kvh, g_kvh); cudaGetSymbolAddress((void**)&kvl, g_kvl);
    cudaGetSymbolAddress((void**)&obh, g_obh); cudaGetSymbolAddress((void**)&obl, g_obl);
    cudaGetSymbolAddress((void**)&wqch, g_wqch); cudaGetSymbolAddress((void**)&wqcl, g_wqcl);
    cudaGetSymbolAddress((void**)&wkch, g_wkch); cudaGetSymbolAddress((void**)&wkcl, g_wkcl);
    cudaGetSymbolAddress((void**)&wvh, g_wvh);   cudaGetSymbolAddress((void**)&wvl, g_wvl);
    cudaGetSymbolAddress((void**)&woh, g_woh);   cudaGetSymbolAddress((void**)&wol, g_wol);
    cudaGetSymbolAddress((void**)&wqrh, g_wqrh); cudaGetSymbolAddress((void**)&wqrl, g_wqrl);
    cudaGetSymbolAddress((void**)&wkrh, g_wkrh); cudaGetSymbolAddress((void**)&wkrl, g_wkrl);
    cudaGetSymbolAddress((void**)&Qhp, g_Qh);   cudaGetSymbolAddress((void**)&Qlp, g_Ql);
    cudaGetSymbolAddress((void**)&Khp, g_Kh);   cudaGetSymbolAddress((void**)&Klp, g_Kl);
    cudaGetSymbolAddress((void**)&Vthp, g_Vth); cudaGetSymbolAddress((void**)&Vtlp, g_Vtl);

    const int GEMM_SMEM = 131072;
    cudaFuncSetAttribute(hmma_gemm<0>, cudaFuncAttributeMaxDynamicSharedMemorySize, GEMM_SMEM);
    cudaFuncSetAttribute(hmma_gemm<1>, cudaFuncAttributeMaxDynamicSharedMemorySize, GEMM_SMEM);
    cudaFuncSetAttribute(hmma_gemm<2>, cudaFuncAttributeMaxDynamicSharedMemorySize, GEMM_SMEM);
    cudaFuncSetAttribute(hmma_gemm<3>, cudaFuncAttributeMaxDynamicSharedMemorySize, GEMM_SMEM);
    cudaFuncSetAttribute(flash_hmma, cudaFuncAttributeMaxDynamicSharedMemorySize, FA_SMEM);

    rope_table_kernel<<<Mm, 32>>>();
    cvt_split<<<(int)(SZ_X / 1024), 256>>>((const float4*)query, (uint2*)qh, (uint2*)ql, (int)(SZ_X / 4));
    cvt_split<<<(int)(SZ_X / 1024), 256>>>((const float4*)kv, (uint2*)kvh, (uint2*)kvl, (int)(SZ_X / 4));
    cvt_split<<<(int)(SZ_W2 / 1024), 256>>>((const float4*)W_QC, (uint2*)wqch, (uint2*)wqcl, (int)(SZ_W2 / 4));
    cvt_split<<<(int)(SZ_W2 / 1024), 256>>>((const float4*)W_KC, (uint2*)wkch, (uint2*)wkcl, (int)(SZ_W2 / 4));
    cvt_split<<<(int)(SZ_W1 / 1024), 256>>>((const float4*)W_QR, (uint2*)wqrh, (uint2*)wqrl, (int)(SZ_W1 / 4));
    cvt_split<<<(int)(SZ_W1 / 1024), 256>>>((const float4*)W_KR, (uint2*)wkrh, (uint2*)wkrl, (int)(SZ_W1 / 4));
    cvt_split<<<(int)(SZ_W2 / 1024), 256>>>((const float4*)W_V, (uint2*)wvh, (uint2*)wvl, (int)(SZ_W2 / 4));
    cvt_split<<<(int)(SZ_W2 / 1024), 256>>>((const float4*)W_O, (uint2*)woh, (uint2*)wol, (int)(SZ_W2 / 4));

    hmma_gemm<1><<<dim3(16, 32), 256, GEMM_SMEM>>>(qh, ql, wqch, wqcl, nullptr, Qhp, Qlp);
    hmma_gemm<2><<<dim3(8, 32), 256, GEMM_SMEM>>>(qh, ql, wqrh, wqrl, nullptr, Qhp, Qlp);
    hmma_gemm<1><<<dim3(16, 32), 256, GEMM_SMEM>>>(kvh, kvl, wkch, wkcl, nullptr, Khp, Klp);
    hmma_gemm<2><<<dim3(8, 32), 256, GEMM_SMEM>>>(kvh, kvl, wkrh, wkrl, nullptr, Khp, Klp);
    hmma_gemm<3><<<dim3(16, 32), 256, GEMM_SMEM>>>(kvh, kvl, wvh, wvl, nullptr, Vthp, Vtlp);

    flash_hmma<<<dim3(16, 32), 256, FA_SMEM>>>(Qhp, Qlp, Khp, Klp, Vthp, Vtlp, obh, obl);

    hmma_gemm<0><<<dim3(16, 32), 256, GEMM_SMEM>>>(obh, obl, woh, wol, out, nullptr, nullptr);
}

// round 12
// speedup vs baseline: 2.5643x; 1.0168x over previous
#include <cuda_runtime.h>
#include <cuda_bf16.h>
#include <math.h>
#include <stdint.h>

// Problem constants
#define Bb   2
#define Mm   2048
#define Dd   2048
#define Hh   16
#define DHh  128
#define DRr  64
#define DQq  192   // concatenated head dim: 128 (C path) + 64 (RoPE path)

// 1/sqrt(192) * log2(e): Q is pre-scaled so S is in exp2 domain
#define SCALE2 0.10411755f

__device__ float g_cos[Mm * DRr];
__device__ float g_sin[Mm * DRr];

// bf16 hi/lo split scratch
#define SZ_X  ((size_t)Bb * Mm * Dd)        // 8388608
#define SZ_W2 ((size_t)2048 * 2048)
#define SZ_W1 ((size_t)1024 * 2048)
#define SZ_QK ((size_t)Bb * Hh * Mm * DQq)  // 12582912
#define SZ_V  ((size_t)Bb * Hh * DHh * Mm)  // 8388608
__device__ __nv_bfloat16 g_qh[SZ_X],  g_ql[SZ_X];
__device__ __nv_bfloat16 g_kvh[SZ_X], g_kvl[SZ_X];
__device__ __nv_bfloat16 g_obh[SZ_X], g_obl[SZ_X];
__device__ __nv_bfloat16 g_wqch[SZ_W2], g_wqcl[SZ_W2];
__device__ __nv_bfloat16 g_wkch[SZ_W2], g_wkcl[SZ_W2];
__device__ __nv_bfloat16 g_wvh[SZ_W2],  g_wvl[SZ_W2];
__device__ __nv_bfloat16 g_woh[SZ_W2],  g_wol[SZ_W2];
__device__ __nv_bfloat16 g_wqrh[SZ_W1], g_wqrl[SZ_W1];
__device__ __nv_bfloat16 g_wkrh[SZ_W1], g_wkrl[SZ_W1];
// attention operands (bf16 hi/lo, written by projection epilogues)
__device__ __nv_bfloat16 g_Qh[SZ_QK], g_Ql[SZ_QK];   // (B,H,M,192), pre-scaled
__device__ __nv_bfloat16 g_Kh[SZ_QK], g_Kl[SZ_QK];   // (B,H,N,192)
__device__ __nv_bfloat16 g_Vth[SZ_V], g_Vtl[SZ_V];   // (B,H,128d,2048s) transposed

// ---------------------------------------------------------------------------
// Helpers (generic sm_80/90 features only — target is sm_103 non-'a')
// ---------------------------------------------------------------------------
__device__ __forceinline__ uint32_t smem_u32(const void* p) {
    uint32_t a;
    asm("{ .reg .u64 t; cvta.to.shared.u64 t, %1; cvt.u32.u64 %0, t; }"
        : "=r"(a) : "l"(p));
    return a;
}
__device__ __forceinline__ void cp16(uint32_t s, const void* g) {
    asm volatile("cp.async.cg.shared.global [%0], [%1], 16;" :: "r"(s), "l"(g));
}
#define CP_COMMIT() asm volatile("cp.async.commit_group;" ::: "memory")
#define CP_WAIT0()  asm volatile("cp.async.wait_group 0;" ::: "memory")
#define CP_WAIT1()  asm volatile("cp.async.wait_group 1;" ::: "memory")

__device__ __forceinline__ void ldmx4(uint32_t r[4], uint32_t a) {
    asm volatile("ldmatrix.sync.aligned.m8n8.x4.shared.b16 {%0,%1,%2,%3}, [%4];"
                 : "=r"(r[0]), "=r"(r[1]), "=r"(r[2]), "=r"(r[3]) : "r"(a));
}
__device__ __forceinline__ void mma16816(float c[4], const uint32_t a[4],
                                         uint32_t b0, uint32_t b1) {
    asm volatile(
        "mma.sync.aligned.m16n8k16.row.col.f32.bf16.bf16.f32 "
        "{%0,%1,%2,%3}, {%4,%5,%6,%7}, {%8,%9}, {%0,%1,%2,%3};"
        : "+f"(c[0]), "+f"(c[1]), "+f"(c[2]), "+f"(c[3])
        : "r"(a[0]), "r"(a[1]), "r"(a[2]), "r"(a[3]), "r"(b0), "r"(b1));
}
// MUFU exp2 (ex2.approx.f32)
__device__ __forceinline__ float ex2_mufu(float x) {
    float r;
    asm("ex2.approx.f32 %0, %1;" : "=f"(r) : "f"(x));
    return r;
}
// Truncation-based hi/lo split primitives.
// hi16(x,y) packed in ONE prmt; lo residual pair in ONE cvt.rn.bf16x2.
__device__ __forceinline__ uint32_t prmt_hi(uint32_t x, uint32_t y) {
    uint32_t r;
    asm("prmt.b32 %0, %1, %2, 0x7632;" : "=r"(r) : "r"(x), "r"(y));
    return r;
}
__device__ __forceinline__ uint32_t cvt_bf16x2_pair(float lo_f, float hi_f) {
    uint32_t r;
    asm("cvt.rn.bf16x2.f32 %0, %1, %2;" : "=r"(r) : "f"(hi_f), "f"(lo_f));
    return r;
}
__device__ __forceinline__ float trunc_bf(float x) {
    return __uint_as_float(__float_as_uint(x) & 0xFFFF0000u);
}
// FMA-pipe exp2 (magic-number round + deg-4 Taylor), rel err ~4e-5, t in [-100, 0]
__device__ __forceinline__ float exp2_poly(float t) {
    t = fmaxf(t, -100.0f);
    float z = __fadd_rn(t, 12582912.0f);
    float n = __fsub_rn(z, 12582912.0f);
    float f = t - n;
    float p = fmaf(f, 0.0096181291f, 0.0555041087f);
    p = fmaf(f, p, 0.2402265069f);
    p = fmaf(f, p, 0.6931471806f);
    p = fmaf(f, p, 1.0f);
    uint32_t sc = (__float_as_uint(z) + (127u - 4194304u)) << 23;
    return p * __uint_as_float(sc);
}

// ---------------------------------------------------------------------------
// fp32 -> bf16 hi/lo split (truncation split: hi+lo == x exactly)
// ---------------------------------------------------------------------------
__global__ void __launch_bounds__(256)
cvt_split(const float4* __restrict__ src, uint2* __restrict__ hi,
          uint2* __restrict__ lo, int n4) {
    int i = blockIdx.x * 256 + threadIdx.x;
    if (i >= n4) return;
    float4 v = src[i];
    uint32_t bx = __float_as_uint(v.x), by = __float_as_uint(v.y);
    uint32_t bz = __float_as_uint(v.z), bw = __float_as_uint(v.w);
    hi[i] = make_uint2(prmt_hi(bx, by), prmt_hi(bz, bw));
    lo[i] = make_uint2(
        cvt_bf16x2_pair(v.x - trunc_bf(v.x), v.y - trunc_bf(v.y)),
        cvt_bf16x2_pair(v.z - trunc_bf(v.z), v.w - trunc_bf(v.w)));
}

// ---------------------------------------------------------------------------
// RoPE table (fp64 angles)
// ---------------------------------------------------------------------------
__global__ void rope_table_kernel() {
    int s = blockIdx.x;
    int i = threadIdx.x;  // 0..31
    double freq = exp(-((double)(2 * i) / 64.0) * log(1000000.0));
    double ang = (double)s * freq;
    float c = (float)cos(ang);
    float sn = (float)sin(ang);
    g_cos[s * 64 + 2 * i] = c;  g_cos[s * 64 + 2 * i + 1] = c;
    g_sin[s * 64 + 2 * i] = sn; g_sin[s * 64 + 2 * i + 1] = sn;
}

// ---------------------------------------------------------------------------
// HMMA bf16x3 NT GEMM: 3-stage cp.async pipeline, one barrier per K-chunk.
// MODE 0: fp32 plain (ldc=2048)   MODE 1: -> Q/K hi+lo (B,H,S,192)[0:128]
// MODE 2: RoPE -> (B,H,S,192)[128:192]   MODE 3: V -> transposed (B,H,128,2048)
// oscale: multiplied into the result before split (Q pre-scaling; 1.0 otherwise)
// ---------------------------------------------------------------------------
__device__ __forceinline__ void load_chunk(uint32_t sb, int tid, int row0, int col0,
        const __nv_bfloat16* Ah, const __nv_bfloat16* Al,
        const __nv_bfloat16* Bh, const __nv_bfloat16* Bl, int c, int stage) {
    const size_t k0b = (size_t)c * 128;
    const uint32_t base = sb + (uint32_t)stage * 65536;
#pragma unroll
    for (int i = 0; i < 4; ++i) {
        int flat = tid + i * 256;
        int row = flat >> 3;
        int cb = (flat & 7) << 4;
        uint32_t so = (uint32_t)(row * 128 + (cb ^ ((row & 7) * 16)));
        const size_t ra = ((size_t)(row0 + row) * Dd) * 2 + k0b + cb;
        const size_t rb = ((size_t)(col0 + row) * Dd) * 2 + k0b + cb;
        cp16(base + so,         (const char*)Ah + ra);
        cp16(base + 16384 + so, (const char*)Al + ra);
        cp16(base + 32768 + so, (const char*)Bh + rb);
        cp16(base + 49152 + so, (const char*)Bl + rb);
    }
}

template <int MODE>
__global__ void __launch_bounds__(256, 1)
hmma_gemm(const __nv_bfloat16* __restrict__ Ah, const __nv_bfloat16* __restrict__ Al,
          const __nv_bfloat16* __restrict__ Bh, const __nv_bfloat16* __restrict__ Bl,
          float* __restrict__ outf,
          __nv_bfloat16* __restrict__ oh, __nv_bfloat16* __restrict__ ol,
          float oscale) {
    extern __shared__ __align__(1024) char smem[];
    const uint32_t sb = smem_u32(smem);
    const int tid = threadIdx.x;
    const int wid = tid >> 5, lane = tid & 31;
    const int wm = wid >> 2, wn = wid & 3;
    const int row0 = blockIdx.y * 128, col0 = blockIdx.x * 128;

    float acc[4][4][4];
#pragma unroll
    for (int mi = 0; mi < 4; ++mi)
#pragma unroll
        for (int ni = 0; ni < 4; ++ni)
#pragma unroll
            for (int k = 0; k < 4; ++k) acc[mi][ni][k] = 0.0f;

    const int aRow = wm * 64 + (lane & 15);
    const int aKs  = (lane >> 4) * 16;
    const int bRow = wn * 32 + ((lane >> 4) << 3) + (lane & 7);
    const int bKs  = ((lane >> 3) & 1) * 16;

    load_chunk(sb, tid, row0, col0, Ah, Al, Bh, Bl, 0, 0);
    CP_COMMIT();
    load_chunk(sb, tid, row0, col0, Ah, Al, Bh, Bl, 1, 1);
    CP_COMMIT();

    int st = 0;
    for (int c = 0; c < 32; ++c) {
        CP_WAIT1();
        __syncthreads();
        if (c + 2 < 32) {
            int st2 = st + 2; if (st2 >= 3) st2 -= 3;
            load_chunk(sb, tid, row0, col0, Ah, Al, Bh, Bl, c + 2, st2);
            CP_COMMIT();
        }
        const uint32_t base = sb + (uint32_t)st * 65536;
#pragma unroll
        for (int ks = 0; ks < 4; ++ks) {
            const int kA = ks * 32 + aKs;
            const int kB = ks * 32 + bKs;
            uint32_t ah[4][4], al[4][4];
#pragma unroll
            for (int mi = 0; mi < 4; ++mi) {
                const int r = aRow + mi * 16;
                const uint32_t off = (uint32_t)(r * 128 + (kA ^ ((r & 7) * 16)));
                ldmx4(ah[mi], base + off);
                ldmx4(al[mi], base + 16384 + off);
            }
            uint32_t bh[2][4], bl[2][4];
#pragma unroll
            for (int np = 0; np < 2; ++np) {
                const int r = bRow + np * 16;
                const uint32_t off = (uint32_t)(r * 128 + (kB ^ ((r & 7) * 16)));
                ldmx4(bh[np], base + 32768 + off);
                ldmx4(bl[np], base + 49152 + off);
            }
#pragma unroll
            for (int mi = 0; mi < 4; ++mi)
#pragma unroll
                for (int ni = 0; ni < 4; ++ni) {
                    const uint32_t* ph = &bh[ni >> 1][(ni & 1) * 2];
                    const uint32_t* pl = &bl[ni >> 1][(ni & 1) * 2];
                    mma16816(acc[mi][ni], ah[mi], ph[0], ph[1]);
                    mma16816(acc[mi][ni], ah[mi], pl[0], pl[1]);
                    mma16816(acc[mi][ni], al[mi], ph[0], ph[1]);
                }
        }
        st = (st == 2) ? 0 : st + 1;
    }

#pragma unroll
    for (int mi = 0; mi < 4; ++mi)
#pragma unroll
        for (int ni = 0; ni < 4; ++ni)
#pragma unroll
            for (int h2 = 0; h2 < 2; ++h2) {
                const int row = row0 + wm * 64 + mi * 16 + (lane >> 2) + h2 * 8;
                const int col = col0 + wn * 32 + ni * 8 + (lane & 3) * 2;
                const float v0 = acc[mi][ni][h2 * 2 + 0];
                const float v1 = acc[mi][ni][h2 * 2 + 1];
                const int b = row >> 11;
                const int ss = row & 2047;
                if (MODE == 0) {
                    *(float2*)(outf + (size_t)row * Dd + col) = make_float2(v0, v1);
                } else if (MODE == 1) {
                    const float y0 = v0 * oscale, y1 = v1 * oscale;
                    const int hH = col >> 7, jj = col & 127;
                    const size_t idx = (((size_t)(b * Hh + hH) * Mm) + ss) * DQq + jj;
                    *(uint32_t*)(oh + idx) = prmt_hi(__float_as_uint(y0), __float_as_uint(y1));
                    *(uint32_t*)(ol + idx) = cvt_bf16x2_pair(y0 - trunc_bf(y0), y1 - trunc_bf(y1));
                } else if (MODE == 2) {
                    const int hH = col >> 6, jr = col & 63;
                    const float cv = g_cos[ss * 64 + jr];
                    const float sv = g_sin[ss * 64 + jr];
                    const float y0 = (v0 * cv - v1 * sv) * oscale;
                    const float y1 = (v1 * cv + v0 * sv) * oscale;
                    const size_t idx = (((size_t)(b * Hh + hH) * Mm) + ss) * DQq + 128 + jr;
                    *(uint32_t*)(oh + idx) = prmt_hi(__float_as_uint(y0), __float_as_uint(y1));
                    *(uint32_t*)(ol + idx) = cvt_bf16x2_pair(y0 - trunc_bf(y0), y1 - trunc_bf(y1));
                } else {  // MODE 3: V transposed (B,H,128,2048)
                    const int hH = col >> 7, jj = col & 127;
                    const size_t idx = (((size_t)(b * Hh + hH) * DHh) + jj) * Mm + ss;
                    oh[idx] = __ushort_as_bfloat16((unsigned short)(__float_as_uint(v0) >> 16));
                    ol[idx] = __float2bfloat16(v0 - trunc_bf(v0));
                    oh[idx + Mm] = __ushort_as_bfloat16((unsigned short)(__float_as_uint(v1) >> 16));
                    ol[idx + Mm] = __float2bfloat16(v1 - trunc_bf(v1));
                }
            }
}

// ---------------------------------------------------------------------------
// Flash attention, HMMA bf16x3. Q pre-scaled by 1/sqrt(192)*log2e -> S in exp2
// domain; softmax uses hybrid MUFU ex2.approx / FMA-pipe poly to balance pipes.
// SMEM: Qh/Ql resident 3x[128x64] (96KB) + K 2-stage [128x64]x2 (64KB)
//       + V^T [128x128] hi/lo (64KB) = 224KB.
// ---------------------------------------------------------------------------
#define SB_QL   49152
#define SB_K    98304
#define SB_VTH  163840
#define SB_VTL  196608
#define FA_SMEM 229376

__device__ __forceinline__ void ld_tile128(uint32_t dst, int tid,
        const __nv_bfloat16* src, int lds) {
#pragma unroll
    for (int i = 0; i < 4; ++i) {
        int flat = tid + i * 256;
        int row = flat >> 3;
        int cb = (flat & 7) << 4;
        uint32_t so = (uint32_t)(row * 128 + (cb ^ ((row & 7) * 16)));
        cp16(dst + so, (const char*)src + (size_t)row * lds * 2 + cb);
    }
}
__device__ __forceinline__ void ld_tile256(uint32_t dst, int tid,
        const __nv_bfloat16* src, int lds) {
#pragma unroll
    for (int i = 0; i < 8; ++i) {
        int flat = tid + i * 256;
        int row = flat >> 4;
        int cb = (flat & 15) << 4;
        uint32_t so = (uint32_t)(row * 256 + (cb ^ ((row & 7) * 16)));
        cp16(dst + so, (const char*)src + (size_t)row * lds * 2 + cb);
    }
}

__global__ void __launch_bounds__(256, 1)
flash_hmma(const __nv_bfloat16* __restrict__ Qh, const __nv_bfloat16* __restrict__ Ql,
           const __nv_bfloat16* __restrict__ Kh, const __nv_bfloat16* __restrict__ Kl,
           const __nv_bfloat16* __restrict__ Vth, const __nv_bfloat16* __restrict__ Vtl,
           __nv_bfloat16* __restrict__ Oh, __nv_bfloat16* __restrict__ Ol) {
    extern __shared__ __align__(1024) char smem[];
    const uint32_t sb = smem_u32(smem);
    const int tid = threadIdx.x;
    const int wid = tid >> 5, lane = tid & 31;
    const int bh = blockIdx.y;
    const int m0 = blockIdx.x * 128;

    const __nv_bfloat16* Qhb = Qh + ((size_t)bh * Mm + m0) * DQq;
    const __nv_bfloat16* Qlb = Ql + ((size_t)bh * Mm + m0) * DQq;
    const __nv_bfloat16* Khb = Kh + (size_t)bh * Mm * DQq;
    const __nv_bfloat16* Klb = Kl + (size_t)bh * Mm * DQq;
    const __nv_bfloat16* Vhb = Vth + (size_t)bh * DHh * Mm;
    const __nv_bfloat16* Vlb = Vtl + (size_t)bh * DHh * Mm;

    float o_acc[16][4];
#pragma unroll
    for (int ni = 0; ni < 16; ++ni)
#pragma unroll
        for (int k = 0; k < 4; ++k) o_acc[ni][k] = 0.0f;
    float mrow0 = -1e30f, mrow1 = -1e30f, lsum0 = 0.0f, lsum1 = 0.0f;

    // prologue: resident Q (3 chunks hi+lo) + K chunk 0
#pragma unroll
    for (int dc = 0; dc < 3; ++dc) {
        ld_tile128(sb + dc * 16384, tid, Qhb + dc * 64, DQq);
        ld_tile128(sb + SB_QL + dc * 16384, tid, Qlb + dc * 64, DQq);
    }
    ld_tile128(sb + SB_K, tid, Khb, DQq);
    ld_tile128(sb + SB_K + 16384, tid, Klb, DQq);
    CP_COMMIT();

    int t = 0;
#pragma unroll 1
    for (int n0i = 0; n0i < 16; ++n0i) {
        float sacc[16][4];
#pragma unroll
        for (int ni = 0; ni < 16; ++ni)
#pragma unroll
            for (int k = 0; k < 4; ++k) sacc[ni][k] = 0.0f;

#pragma unroll 1
        for (int dc = 0; dc < 3; ++dc) {
            CP_WAIT0();
            __syncthreads();
            // issue chunk t+1 (+ V tile when (t+1)%3==2)
            if (t + 1 < 48) {
                const int nn = (t + 1) / 3, ndc = (t + 1) % 3;
                const uint32_t kst = SB_K + (uint32_t)((t + 1) & 1) * 32768;
                ld_tile128(sb + kst, tid, Khb + (size_t)(nn * 128) * DQq + ndc * 64, DQq);
                ld_tile128(sb + kst + 16384, tid, Klb + (size_t)(nn * 128) * DQq + ndc * 64, DQq);
                if (ndc == 2) {
                    ld_tile256(sb + SB_VTH, tid, Vhb + nn * 128, Mm);
                    ld_tile256(sb + SB_VTL, tid, Vlb + nn * 128, Mm);
                }
                CP_COMMIT();
            }
            // S += Q_chunk @ K_chunk^T  (bf16x3)
            const uint32_t kbase = sb + SB_K + (uint32_t)(t & 1) * 32768;
            const uint32_t qbase = sb + (uint32_t)dc * 16384;
            const uint32_t qlbase = sb + SB_QL + (uint32_t)dc * 16384;
#pragma unroll
            for (int ks = 0; ks < 4; ++ks) {
                const int rA = wid * 16 + (lane & 15);
                const uint32_t offA = (uint32_t)(rA * 128 +
                    ((ks * 32 + (lane >> 4) * 16) ^ ((rA & 7) * 16)));
                uint32_t ah[4], al2[4];
                ldmx4(ah, qbase + offA);
                ldmx4(al2, qlbase + offA);
#pragma unroll
                for (int np = 0; np < 8; ++np) {
                    const int rB = np * 16 + ((lane >> 4) << 3) + (lane & 7);
                    const uint32_t offB = (uint32_t)(rB * 128 +
                        ((ks * 32 + ((lane >> 3) & 1) * 16) ^ ((rB & 7) * 16)));
                    uint32_t bh4[4], bl4[4];
                    ldmx4(bh4, kbase + offB);
                    ldmx4(bl4, kbase + 16384 + offB);
                    mma16816(sacc[np * 2], ah, bh4[0], bh4[1]);
                    mma16816(sacc[np * 2], ah, bl4[0], bl4[1]);
                    mma16816(sacc[np * 2], al2, bh4[0], bh4[1]);
                    mma16816(sacc[np * 2 + 1], ah, bh4[2], bh4[3]);
                    mma16816(sacc[np * 2 + 1], ah, bl4[2], bl4[3]);
                    mma16816(sacc[np * 2 + 1], al2, bh4[2], bh4[3]);
                }
            }
            ++t;
        }

        // --- online softmax in exp2 domain (S pre-scaled via Q) ---
        float mx0 = -1e30f, mx1 = -1e30f;
#pragma unroll
        for (int ni = 0; ni < 16; ++ni) {
            mx0 = fmaxf(mx0, fmaxf(sacc[ni][0], sacc[ni][1]));
            mx1 = fmaxf(mx1, fmaxf(sacc[ni][2], sacc[ni][3]));
        }
        mx0 = fmaxf(mx0, __shfl_xor_sync(0xffffffffu, mx0, 1));
        mx0 = fmaxf(mx0, __shfl_xor_sync(0xffffffffu, mx0, 2));
        mx1 = fmaxf(mx1, __shfl_xor_sync(0xffffffffu, mx1, 1));
        mx1 = fmaxf(mx1, __shfl_xor_sync(0xffffffffu, mx1, 2));
        const float mn0 = fmaxf(mrow0, mx0), mn1 = fmaxf(mrow1, mx1);
        const float cr0 = ex2_mufu(mrow0 - mn0), cr1 = ex2_mufu(mrow1 - mn1);
        mrow0 = mn0; mrow1 = mn1;
        float ps0 = 0.0f, ps1 = 0.0f;
#pragma unroll
        for (int ni = 0; ni < 16; ++ni) {
            sacc[ni][0] = ex2_mufu(sacc[ni][0] - mn0);    // MUFU pipe
            sacc[ni][1] = exp2_poly(sacc[ni][1] - mn0);   // FMA pipe
            sacc[ni][2] = ex2_mufu(sacc[ni][2] - mn1);
            sacc[ni][3] = exp2_poly(sacc[ni][3] - mn1);
            ps0 += sacc[ni][0] + sacc[ni][1];
            ps1 += sacc[ni][2] + sacc[ni][3];
        }
        ps0 += __shfl_xor_sync(0xffffffffu, ps0, 1);
        ps0 += __shfl_xor_sync(0xffffffffu, ps0, 2);
        ps1 += __shfl_xor_sync(0xffffffffu, ps1, 1);
        ps1 += __shfl_xor_sync(0xffffffffu, ps1, 2);
        lsum0 = lsum0 * cr0 + ps0;
        lsum1 = lsum1 * cr1 + ps1;
#pragma unroll
        for (int ni = 0; ni < 16; ++ni) {
            o_acc[ni][0] *= cr0; o_acc[ni][1] *= cr0;
            o_acc[ni][2] *= cr1; o_acc[ni][3] *= cr1;
        }

        // --- O += P @ V  (P frags direct from S accumulators; trunc split) ---
#pragma unroll 1
        for (int ki = 0; ki < 8; ++ki) {
            uint32_t aph[4], apl[4];
#pragma unroll
            for (int half = 0; half < 2; ++half) {
                const float* p = sacc[2 * ki + half];
                aph[half * 2 + 0] = prmt_hi(__float_as_uint(p[0]), __float_as_uint(p[1]));
                aph[half * 2 + 1] = prmt_hi(__float_as_uint(p[2]), __float_as_uint(p[3]));
                apl[half * 2 + 0] = cvt_bf16x2_pair(p[0] - trunc_bf(p[0]), p[1] - trunc_bf(p[1]));
                apl[half * 2 + 1] = cvt_bf16x2_pair(p[2] - trunc_bf(p[2]), p[3] - trunc_bf(p[3]));
            }
#pragma unroll
            for (int np = 0; np < 8; ++np) {
                const int rB = np * 16 + ((lane >> 4) << 3) + (lane & 7);
                const uint32_t offB = (uint32_t)(rB * 256 +
                    ((ki * 32 + ((lane >> 3) & 1) * 16) ^ ((rB & 7) * 16)));
                uint32_t vh4[4], vl4[4];
                ldmx4(vh4, sb + SB_VTH + offB);
                ldmx4(vl4, sb + SB_VTL + offB);
                mma16816(o_acc[np * 2], aph, vh4[0], vh4[1]);
                mma16816(o_acc[np * 2], aph, vl4[0], vl4[1]);
                mma16816(o_acc[np * 2], apl, vh4[0], vh4[1]);
                mma16816(o_acc[np * 2 + 1], aph, vh4[2], vh4[3]);
                mma16816(o_acc[np * 2 + 1], aph, vl4[2], vl4[3]);
                mma16816(o_acc[np * 2 + 1], apl, vh4[2], vh4[3]);
            }
        }
    }

    // --- epilogue: normalize, trunc-split hi/lo, write (B,M,2048) ---
    const float inv0 = 1.0f / lsum0, inv1 = 1.0f / lsum1;
    const int b = bh >> 4, h = bh & 15;
    const int g = lane >> 2, t2 = lane & 3;
    const int mrow = m0 + wid * 16 + g;
#pragma unroll
    for (int ni = 0; ni < 16; ++ni) {
        const int col = h * DHh + ni * 8 + t2 * 2;
        const float y0 = o_acc[ni][0] * inv0, y1 = o_acc[ni][1] * inv0;
        const float z0 = o_acc[ni][2] * inv1, z1 = o_acc[ni][3] * inv1;
        const size_t i0 = ((size_t)(b * Mm + mrow)) * Dd + col;
        const size_t i1 = ((size_t)(b * Mm + mrow + 8)) * Dd + col;
        *(uint32_t*)(Oh + i0) = prmt_hi(__float_as_uint(y0), __float_as_uint(y1));
        *(uint32_t*)(Ol + i0) = cvt_bf16x2_pair(y0 - trunc_bf(y0), y1 - trunc_bf(y1));
        *(uint32_t*)(Oh + i1) = prmt_hi(__float_as_uint(z0), __float_as_uint(z1));
        *(uint32_t*)(Ol + i1) = cvt_bf16x2_pair(z0 - trunc_bf(z0), z1 - trunc_bf(z1));
    }
}

// ---------------------------------------------------------------------------
extern "C" void kernel_launch(void* const* d_in, const int* in_sizes, int n_in,
                              void* d_out, int out_size) {
    (void)in_sizes; (void)n_in; (void)out_size;
    const float* query = (const float*)d_in[0];
    const float* kv    = (const float*)d_in[1];
    const float* W_QC  = (const float*)d_in[2];
    const float* W_KC  = (const float*)d_in[3];
    const float* W_QR  = (const float*)d_in[4];
    const float* W_KR  = (const float*)d_in[5];
    const float* W_V   = (const float*)d_in[6];
    const float* W_O   = (const float*)d_in[7];
    float* out = (float*)d_out;

    __nv_bfloat16 *qh, *ql, *kvh, *kvl, *obh, *obl;
    __nv_bfloat16 *wqch, *wqcl, *wkch, *wkcl, *wvh, *wvl, *woh, *wol;
    __nv_bfloat16 *wqrh, *wqrl, *wkrh, *wkrl;
    __nv_bfloat16 *Qhp, *Qlp, *Khp, *Klp, *Vthp, *Vtlp;
    cudaGetSymbolAddress((void**)&qh, g_qh);   cudaGetSymbolAddress((void**)&ql, g_ql);
    cudaGetSymbolAddress((void**)&kvh, g_kvh); cudaGetSymbolAddress((void**)&kvl, g_kvl);
    cudaGetSymbolAddress((void**)&obh, g_obh); cudaGetSymbolAddress((void**)&obl, g_obl);
    cudaGetSymbolAddress((void**)&wqch, g_wqch); cudaGetSymbolAddress((void**)&wqcl, g_wqcl);
    cudaGetSymbolAddress((void**)&wkch, g_wkch); cudaGetSymbolAddress((void**)&wkcl, g_wkcl);
    cudaGetSymbolAddress((void**)&wvh, g_wvh);   cudaGetSymbolAddress((void**)&wvl, g_wvl);
    cudaGetSymbolAddress((void**)&woh, g_woh);   cudaGetSymbolAddress((void**)&wol, g_wol);
    cudaGetSymbolAddress((void**)&wqrh, g_wqrh); cudaGetSymbolAddress((void**)&wqrl, g_wqrl);
    cudaGetSymbolAddress((void**)&wkrh, g_wkrh); cudaGetSymbolAddress((void**)&wkrl, g_wkrl);
    cudaGetSymbolAddress((void**)&Qhp, g_Qh);   cudaGetSymbolAddress((void**)&Qlp, g_Ql);
    cudaGetSymbolAddress((void**)&Khp, g_Kh);   cudaGetSymbolAddress((void**)&Klp, g_Kl);
    cudaGetSymbolAddress((void**)&Vthp, g_Vth); cudaGetSymbolAddress((void**)&Vtlp, g_Vtl);

    const int GEMM_SMEM = 196608;  // 3 stages x 64KB
    cudaFuncSetAttribute(hmma_gemm<0>, cudaFuncAttributeMaxDynamicSharedMemorySize, GEMM_SMEM);
    cudaFuncSetAttribute(hmma_gemm<1>, cudaFuncAttributeMaxDynamicSharedMemorySize, GEMM_SMEM);
    cudaFuncSetAttribute(hmma_gemm<2>, cudaFuncAttributeMaxDynamicSharedMemorySize, GEMM_SMEM);
    cudaFuncSetAttribute(hmma_gemm<3>, cudaFuncAttributeMaxDynamicSharedMemorySize, GEMM_SMEM);
    cudaFuncSetAttribute(flash_hmma, cudaFuncAttributeMaxDynamicSharedMemorySize, FA_SMEM);

    rope_table_kernel<<<Mm, 32>>>();
    cvt_split<<<(int)(SZ_X / 1024), 256>>>((const float4*)query, (uint2*)qh, (uint2*)ql, (int)(SZ_X / 4));
    cvt_split<<<(int)(SZ_X / 1024), 256>>>((const float4*)kv, (uint2*)kvh, (uint2*)kvl, (int)(SZ_X / 4));
    cvt_split<<<(int)(SZ_W2 / 1024), 256>>>((const float4*)W_QC, (uint2*)wqch, (uint2*)wqcl, (int)(SZ_W2 / 4));
    cvt_split<<<(int)(SZ_W2 / 1024), 256>>>((const float4*)W_KC, (uint2*)wkch, (uint2*)wkcl, (int)(SZ_W2 / 4));
    cvt_split<<<(int)(SZ_W1 / 1024), 256>>>((const float4*)W_QR, (uint2*)wqrh, (uint2*)wqrl, (int)(SZ_W1 / 4));
    cvt_split<<<(int)(SZ_W1 / 1024), 256>>>((const float4*)W_KR, (uint2*)wkrh, (uint2*)wkrl, (int)(SZ_W1 / 4));
    cvt_split<<<(int)(SZ_W2 / 1024), 256>>>((const float4*)W_V, (uint2*)wvh, (uint2*)wvl, (int)(SZ_W2 / 4));
    cvt_split<<<(int)(SZ_W2 / 1024), 256>>>((const float4*)W_O, (uint2*)woh, (uint2*)wol, (int)(SZ_W2 / 4));

    // Projections: Q pre-scaled by 1/sqrt(192)*log2(e); K/V unscaled
    hmma_gemm<1><<<dim3(16, 32), 256, GEMM_SMEM>>>(qh, ql, wqch, wqcl, nullptr, Qhp, Qlp, SCALE2);
    hmma_gemm<2><<<dim3(8, 32), 256, GEMM_SMEM>>>(qh, ql, wqrh, wqrl, nullptr, Qhp, Qlp, SCALE2);
    hmma_gemm<1><<<dim3(16, 32), 256, GEMM_SMEM>>>(kvh, kvl, wkch, wkcl, nullptr, Khp, Klp, 1.0f);
    hmma_gemm<2><<<dim3(8, 32), 256, GEMM_SMEM>>>(kvh, kvl, wkrh, wkrl, nullptr, Khp, Klp, 1.0f);
    hmma_gemm<3><<<dim3(16, 32), 256, GEMM_SMEM>>>(kvh, kvl, wvh, wvl, nullptr, Vthp, Vtlp, 1.0f);

    flash_hmma<<<dim3(16, 32), 256, FA_SMEM>>>(Qhp, Qlp, Khp, Klp, Vthp, Vtlp, obh, obl);

    hmma_gemm<0><<<dim3(16, 32), 256, GEMM_SMEM>>>(obh, obl, woh, wol, out, nullptr, nullptr, 1.0f);
}

// round 13
// speedup vs baseline: 2.7204x; 1.0609x over previous
#include <cuda_runtime.h>
#include <cuda_bf16.h>
#include <cuda_fp16.h>
#include <math.h>
#include <stdint.h>

// Problem constants
#define Bb   2
#define Mm   2048
#define Dd   2048
#define Hh   16
#define DHh  128
#define DRr  64
#define DQq  192   // concatenated head dim: 128 (C path) + 64 (RoPE path)

// 1/sqrt(192) * log2(e): Q is pre-scaled so S is in exp2 domain
#define SCALE2 0.10411755f

__device__ float g_cos[Mm * DRr];
__device__ float g_sin[Mm * DRr];

// bf16 hi/lo split scratch (projection GEMM inputs, bf16x3 path)
#define SZ_X  ((size_t)Bb * Mm * Dd)        // 8388608
#define SZ_W2 ((size_t)2048 * 2048)
#define SZ_W1 ((size_t)1024 * 2048)
#define SZ_QK ((size_t)Bb * Hh * Mm * DQq)  // 12582912
#define SZ_V  ((size_t)Bb * Hh * DHh * Mm)  // 8388608
__device__ __nv_bfloat16 g_qh[SZ_X],  g_ql[SZ_X];
__device__ __nv_bfloat16 g_kvh[SZ_X], g_kvl[SZ_X];
__device__ __nv_bfloat16 g_obh[SZ_X], g_obl[SZ_X];
__device__ __nv_bfloat16 g_wqch[SZ_W2], g_wqcl[SZ_W2];
__device__ __nv_bfloat16 g_wkch[SZ_W2], g_wkcl[SZ_W2];
__device__ __nv_bfloat16 g_wvh[SZ_W2],  g_wvl[SZ_W2];
__device__ __nv_bfloat16 g_woh[SZ_W2],  g_wol[SZ_W2];
__device__ __nv_bfloat16 g_wqrh[SZ_W1], g_wqrl[SZ_W1];
__device__ __nv_bfloat16 g_wkrh[SZ_W1], g_wkrl[SZ_W1];
// attention operands (fp16, written by projection epilogues)
__device__ __half g_Qh[SZ_QK], g_Ql[SZ_QK];  // (B,H,M,192) pre-scaled, hi+lo
__device__ __half g_Kh[SZ_QK];               // (B,H,N,192) single fp16
__device__ __half g_Vth[SZ_V], g_Vtl[SZ_V];  // (B,H,128d,2048s) transposed hi+lo

// ---------------------------------------------------------------------------
// Helpers (generic sm_80/90 features only — target is sm_103 non-'a')
// ---------------------------------------------------------------------------
__device__ __forceinline__ uint32_t smem_u32(const void* p) {
    uint32_t a;
    asm("{ .reg .u64 t; cvta.to.shared.u64 t, %1; cvt.u32.u64 %0, t; }"
        : "=r"(a) : "l"(p));
    return a;
}
__device__ __forceinline__ void cp16(uint32_t s, const void* g) {
    asm volatile("cp.async.cg.shared.global [%0], [%1], 16;" :: "r"(s), "l"(g));
}
#define CP_COMMIT() asm volatile("cp.async.commit_group;" ::: "memory")
#define CP_WAIT0()  asm volatile("cp.async.wait_group 0;" ::: "memory")
#define CP_WAIT1()  asm volatile("cp.async.wait_group 1;" ::: "memory")

__device__ __forceinline__ void ldmx4(uint32_t r[4], uint32_t a) {
    asm volatile("ldmatrix.sync.aligned.m8n8.x4.shared.b16 {%0,%1,%2,%3}, [%4];"
                 : "=r"(r[0]), "=r"(r[1]), "=r"(r[2]), "=r"(r[3]) : "r"(a));
}
__device__ __forceinline__ void mma16816(float c[4], const uint32_t a[4],
                                         uint32_t b0, uint32_t b1) {
    asm volatile(
        "mma.sync.aligned.m16n8k16.row.col.f32.bf16.bf16.f32 "
        "{%0,%1,%2,%3}, {%4,%5,%6,%7}, {%8,%9}, {%0,%1,%2,%3};"
        : "+f"(c[0]), "+f"(c[1]), "+f"(c[2]), "+f"(c[3])
        : "r"(a[0]), "r"(a[1]), "r"(a[2]), "r"(a[3]), "r"(b0), "r"(b1));
}
__device__ __forceinline__ void mma16816h(float c[4], const uint32_t a[4],
                                          uint32_t b0, uint32_t b1) {
    asm volatile(
        "mma.sync.aligned.m16n8k16.row.col.f32.f16.f16.f32 "
        "{%0,%1,%2,%3}, {%4,%5,%6,%7}, {%8,%9}, {%0,%1,%2,%3};"
        : "+f"(c[0]), "+f"(c[1]), "+f"(c[2]), "+f"(c[3])
        : "r"(a[0]), "r"(a[1]), "r"(a[2]), "r"(a[3]), "r"(b0), "r"(b1));
}
// MUFU exp2 (ex2.approx.f32)
__device__ __forceinline__ float ex2_mufu(float x) {
    float r;
    asm("ex2.approx.f32 %0, %1;" : "=f"(r) : "f"(x));
    return r;
}
// Truncation-based bf16 hi/lo split primitives (projection GEMM path).
__device__ __forceinline__ uint32_t prmt_hi(uint32_t x, uint32_t y) {
    uint32_t r;
    asm("prmt.b32 %0, %1, %2, 0x7632;" : "=r"(r) : "r"(x), "r"(y));
    return r;
}
__device__ __forceinline__ uint32_t cvt_bf16x2_pair(float lo_f, float hi_f) {
    uint32_t r;
    asm("cvt.rn.bf16x2.f32 %0, %1, %2;" : "=r"(r) : "f"(hi_f), "f"(lo_f));
    return r;
}
__device__ __forceinline__ float trunc_bf(float x) {
    return __uint_as_float(__float_as_uint(x) & 0xFFFF0000u);
}
// fp16 pack: x -> low half, y -> high half
__device__ __forceinline__ uint32_t pack_f16x2(float x, float y) {
    __half2 h = __float22half2_rn(make_float2(x, y));
    return *reinterpret_cast<uint32_t*>(&h);
}
// FMA-pipe exp2 (magic-number round + deg-4 Taylor), rel err ~4e-5, t in [-100, 0]
__device__ __forceinline__ float exp2_poly(float t) {
    t = fmaxf(t, -100.0f);
    float z = __fadd_rn(t, 12582912.0f);
    float n = __fsub_rn(z, 12582912.0f);
    float f = t - n;
    float p = fmaf(f, 0.0096181291f, 0.0555041087f);
    p = fmaf(f, p, 0.2402265069f);
    p = fmaf(f, p, 0.6931471806f);
    p = fmaf(f, p, 1.0f);
    uint32_t sc = (__float_as_uint(z) + (127u - 4194304u)) << 23;
    return p * __uint_as_float(sc);
}

// ---------------------------------------------------------------------------
// fp32 -> bf16 hi/lo split (truncation split: hi+lo == x exactly)
// ---------------------------------------------------------------------------
__global__ void __launch_bounds__(256)
cvt_split(const float4* __restrict__ src, uint2* __restrict__ hi,
          uint2* __restrict__ lo, int n4) {
    int i = blockIdx.x * 256 + threadIdx.x;
    if (i >= n4) return;
    float4 v = src[i];
    uint32_t bx = __float_as_uint(v.x), by = __float_as_uint(v.y);
    uint32_t bz = __float_as_uint(v.z), bw = __float_as_uint(v.w);
    hi[i] = make_uint2(prmt_hi(bx, by), prmt_hi(bz, bw));
    lo[i] = make_uint2(
        cvt_bf16x2_pair(v.x - trunc_bf(v.x), v.y - trunc_bf(v.y)),
        cvt_bf16x2_pair(v.z - trunc_bf(v.z), v.w - trunc_bf(v.w)));
}

// ---------------------------------------------------------------------------
// RoPE table (fp64 angles)
// ---------------------------------------------------------------------------
__global__ void rope_table_kernel() {
    int s = blockIdx.x;
    int i = threadIdx.x;  // 0..31
    double freq = exp(-((double)(2 * i) / 64.0) * log(1000000.0));
    double ang = (double)s * freq;
    float c = (float)cos(ang);
    float sn = (float)sin(ang);
    g_cos[s * 64 + 2 * i] = c;  g_cos[s * 64 + 2 * i + 1] = c;
    g_sin[s * 64 + 2 * i] = sn; g_sin[s * 64 + 2 * i + 1] = sn;
}

// ---------------------------------------------------------------------------
// HMMA bf16x3 NT GEMM: 3-stage cp.async pipeline.
// MODE 0: fp32 plain (ldc=2048)
// MODE 1: -> fp16 (B,H,S,192)[0:128]; ol!=null => hi/lo split (Q), else single (K)
// MODE 2: RoPE -> fp16 (B,H,S,192)[128:192]; same hi/lo rule
// MODE 3: V -> fp16 hi/lo transposed (B,H,128,2048)
// oscale: multiplied into the result before conversion (Q pre-scaling)
// ---------------------------------------------------------------------------
__device__ __forceinline__ void load_chunk(uint32_t sb, int tid, int row0, int col0,
        const __nv_bfloat16* Ah, const __nv_bfloat16* Al,
        const __nv_bfloat16* Bh, const __nv_bfloat16* Bl, int c, int stage) {
    const size_t k0b = (size_t)c * 128;
    const uint32_t base = sb + (uint32_t)stage * 65536;
#pragma unroll
    for (int i = 0; i < 4; ++i) {
        int flat = tid + i * 256;
        int row = flat >> 3;
        int cb = (flat & 7) << 4;
        uint32_t so = (uint32_t)(row * 128 + (cb ^ ((row & 7) * 16)));
        const size_t ra = ((size_t)(row0 + row) * Dd) * 2 + k0b + cb;
        const size_t rb = ((size_t)(col0 + row) * Dd) * 2 + k0b + cb;
        cp16(base + so,         (const char*)Ah + ra);
        cp16(base + 16384 + so, (const char*)Al + ra);
        cp16(base + 32768 + so, (const char*)Bh + rb);
        cp16(base + 49152 + so, (const char*)Bl + rb);
    }
}

template <int MODE>
__global__ void __launch_bounds__(256, 1)
hmma_gemm(const __nv_bfloat16* __restrict__ Ah, const __nv_bfloat16* __restrict__ Al,
          const __nv_bfloat16* __restrict__ Bh, const __nv_bfloat16* __restrict__ Bl,
          float* __restrict__ outf,
          __half* __restrict__ oh, __half* __restrict__ ol,
          float oscale) {
    extern __shared__ __align__(1024) char smem[];
    const uint32_t sb = smem_u32(smem);
    const int tid = threadIdx.x;
    const int wid = tid >> 5, lane = tid & 31;
    const int wm = wid >> 2, wn = wid & 3;
    const int row0 = blockIdx.y * 128, col0 = blockIdx.x * 128;

    float acc[4][4][4];
#pragma unroll
    for (int mi = 0; mi < 4; ++mi)
#pragma unroll
        for (int ni = 0; ni < 4; ++ni)
#pragma unroll
            for (int k = 0; k < 4; ++k) acc[mi][ni][k] = 0.0f;

    const int aRow = wm * 64 + (lane & 15);
    const int aKs  = (lane >> 4) * 16;
    const int bRow = wn * 32 + ((lane >> 4) << 3) + (lane & 7);
    const int bKs  = ((lane >> 3) & 1) * 16;

    load_chunk(sb, tid, row0, col0, Ah, Al, Bh, Bl, 0, 0);
    CP_COMMIT();
    load_chunk(sb, tid, row0, col0, Ah, Al, Bh, Bl, 1, 1);
    CP_COMMIT();

    int st = 0;
    for (int c = 0; c < 32; ++c) {
        CP_WAIT1();
        __syncthreads();
        if (c + 2 < 32) {
            int st2 = st + 2; if (st2 >= 3) st2 -= 3;
            load_chunk(sb, tid, row0, col0, Ah, Al, Bh, Bl, c + 2, st2);
            CP_COMMIT();
        }
        const uint32_t base = sb + (uint32_t)st * 65536;
#pragma unroll
        for (int ks = 0; ks < 4; ++ks) {
            const int kA = ks * 32 + aKs;
            const int kB = ks * 32 + bKs;
            uint32_t ah[4][4], al[4][4];
#pragma unroll
            for (int mi = 0; mi < 4; ++mi) {
                const int r = aRow + mi * 16;
                const uint32_t off = (uint32_t)(r * 128 + (kA ^ ((r & 7) * 16)));
                ldmx4(ah[mi], base + off);
                ldmx4(al[mi], base + 16384 + off);
            }
            uint32_t bh[2][4], bl[2][4];
#pragma unroll
            for (int np = 0; np < 2; ++np) {
                const int r = bRow + np * 16;
                const uint32_t off = (uint32_t)(r * 128 + (kB ^ ((r & 7) * 16)));
                ldmx4(bh[np], base + 32768 + off);
                ldmx4(bl[np], base + 49152 + off);
            }
#pragma unroll
            for (int mi = 0; mi < 4; ++mi)
#pragma unroll
                for (int ni = 0; ni < 4; ++ni) {
                    const uint32_t* ph = &bh[ni >> 1][(ni & 1) * 2];
                    const uint32_t* pl = &bl[ni >> 1][(ni & 1) * 2];
                    mma16816(acc[mi][ni], ah[mi], ph[0], ph[1]);
                    mma16816(acc[mi][ni], ah[mi], pl[0], pl[1]);
                    mma16816(acc[mi][ni], al[mi], ph[0], ph[1]);
                }
        }
        st = (st == 2) ? 0 : st + 1;
    }

#pragma unroll
    for (int mi = 0; mi < 4; ++mi)
#pragma unroll
        for (int ni = 0; ni < 4; ++ni)
#pragma unroll
            for (int h2 = 0; h2 < 2; ++h2) {
                const int row = row0 + wm * 64 + mi * 16 + (lane >> 2) + h2 * 8;
                const int col = col0 + wn * 32 + ni * 8 + (lane & 3) * 2;
                const float v0 = acc[mi][ni][h2 * 2 + 0];
                const float v1 = acc[mi][ni][h2 * 2 + 1];
                const int b = row >> 11;
                const int ss = row & 2047;
                if (MODE == 0) {
                    *(float2*)(outf + (size_t)row * Dd + col) = make_float2(v0, v1);
                } else if (MODE == 1 || MODE == 2) {
                    float y0, y1;
                    size_t idx;
                    if (MODE == 1) {
                        y0 = v0 * oscale; y1 = v1 * oscale;
                        const int hH = col >> 7, jj = col & 127;
                        idx = (((size_t)(b * Hh + hH) * Mm) + ss) * DQq + jj;
                    } else {
                        const int hH = col >> 6, jr = col & 63;
                        const float cv = g_cos[ss * 64 + jr];
                        const float sv = g_sin[ss * 64 + jr];
                        y0 = (v0 * cv - v1 * sv) * oscale;
                        y1 = (v1 * cv + v0 * sv) * oscale;
                        idx = (((size_t)(b * Hh + hH) * Mm) + ss) * DQq + 128 + jr;
                    }
                    __half2 hh = __float22half2_rn(make_float2(y0, y1));
                    *(__half2*)(oh + idx) = hh;
                    if (ol) {
                        float2 hf = __half22float2(hh);
                        *(uint32_t*)(ol + idx) = pack_f16x2(y0 - hf.x, y1 - hf.y);
                    }
                } else {  // MODE 3: V transposed (B,H,128,2048), fp16 hi/lo
                    const int hH = col >> 7, jj = col & 127;
                    const size_t idx = (((size_t)(b * Hh + hH) * DHh) + jj) * Mm + ss;
                    __half h0 = __float2half_rn(v0);
                    oh[idx] = h0;
                    ol[idx] = __float2half_rn(v0 - __half2float(h0));
                    __half h1 = __float2half_rn(v1);
                    oh[idx + Mm] = h1;
                    ol[idx + Mm] = __float2half_rn(v1 - __half2float(h1));
                }
            }
}

// ---------------------------------------------------------------------------
// Flash attention, fp16 two-term HMMA.
//   S = Qh*K + Ql*K   (Q fp16 hi/lo, K single fp16)     2 MMAs per frag
//   O += P*Vh + P*Vl  (P single fp16, V fp16 hi/lo)     2 MMAs per frag
// fp16 x fp16 products are exact in fp32 -> error = input quantization only.
// SMEM: Qh/Ql resident 3x[128x64] (96KB) + K 2-stage 16KB x2 (32KB)
//       + V^T [128x128] hi/lo (64KB) = 192KB.
// ---------------------------------------------------------------------------
#define SB_QL   49152
#define SB_K    98304
#define SB_VTH  131072
#define SB_VTL  163840
#define FA_SMEM 196608

__device__ __forceinline__ void ld_tile128(uint32_t dst, int tid,
        const __half* src, int lds) {
#pragma unroll
    for (int i = 0; i < 4; ++i) {
        int flat = tid + i * 256;
        int row = flat >> 3;
        int cb = (flat & 7) << 4;
        uint32_t so = (uint32_t)(row * 128 + (cb ^ ((row & 7) * 16)));
        cp16(dst + so, (const char*)src + (size_t)row * lds * 2 + cb);
    }
}
__device__ __forceinline__ void ld_tile256(uint32_t dst, int tid,
        const __half* src, int lds) {
#pragma unroll
    for (int i = 0; i < 8; ++i) {
        int flat = tid + i * 256;
        int row = flat >> 4;
        int cb = (flat & 15) << 4;
        uint32_t so = (uint32_t)(row * 256 + (cb ^ ((row & 7) * 16)));
        cp16(dst + so, (const char*)src + (size_t)row * lds * 2 + cb);
    }
}

__global__ void __launch_bounds__(256, 1)
flash_hmma(const __half* __restrict__ Qh, const __half* __restrict__ Ql,
           const __half* __restrict__ Kh,
           const __half* __restrict__ Vth, const __half* __restrict__ Vtl,
           __nv_bfloat16* __restrict__ Oh, __nv_bfloat16* __restrict__ Ol) {
    extern __shared__ __align__(1024) char smem[];
    const uint32_t sb = smem_u32(smem);
    const int tid = threadIdx.x;
    const int wid = tid >> 5, lane = tid & 31;
    const int bh = blockIdx.y;
    const int m0 = blockIdx.x * 128;

    const __half* Qhb = Qh + ((size_t)bh * Mm + m0) * DQq;
    const __half* Qlb = Ql + ((size_t)bh * Mm + m0) * DQq;
    const __half* Khb = Kh + (size_t)bh * Mm * DQq;
    const __half* Vhb = Vth + (size_t)bh * DHh * Mm;
    const __half* Vlb = Vtl + (size_t)bh * DHh * Mm;

    float o_acc[16][4];
#pragma unroll
    for (int ni = 0; ni < 16; ++ni)
#pragma unroll
        for (int k = 0; k < 4; ++k) o_acc[ni][k] = 0.0f;
    float mrow0 = -1e30f, mrow1 = -1e30f, lsum0 = 0.0f, lsum1 = 0.0f;

    // prologue: resident Q (3 chunks hi+lo) + K chunk 0
#pragma unroll
    for (int dc = 0; dc < 3; ++dc) {
        ld_tile128(sb + dc * 16384, tid, Qhb + dc * 64, DQq);
        ld_tile128(sb + SB_QL + dc * 16384, tid, Qlb + dc * 64, DQq);
    }
    ld_tile128(sb + SB_K, tid, Khb, DQq);
    CP_COMMIT();

    int t = 0;
#pragma unroll 1
    for (int n0i = 0; n0i < 16; ++n0i) {
        float sacc[16][4];
#pragma unroll
        for (int ni = 0; ni < 16; ++ni)
#pragma unroll
            for (int k = 0; k < 4; ++k) sacc[ni][k] = 0.0f;

#pragma unroll 1
        for (int dc = 0; dc < 3; ++dc) {
            CP_WAIT0();
            __syncthreads();
            // issue chunk t+1 (+ V tiles when (t+1)%3==2)
            if (t + 1 < 48) {
                const int nn = (t + 1) / 3, ndc = (t + 1) % 3;
                const uint32_t kst = SB_K + (uint32_t)((t + 1) & 1) * 16384;
                ld_tile128(sb + kst, tid, Khb + (size_t)(nn * 128) * DQq + ndc * 64, DQq);
                if (ndc == 2) {
                    ld_tile256(sb + SB_VTH, tid, Vhb + nn * 128, Mm);
                    ld_tile256(sb + SB_VTL, tid, Vlb + nn * 128, Mm);
                }
                CP_COMMIT();
            }
            // S += Qh@K^T + Ql@K^T   (fp16 x2)
            const uint32_t kbase = sb + SB_K + (uint32_t)(t & 1) * 16384;
            const uint32_t qbase = sb + (uint32_t)dc * 16384;
            const uint32_t qlbase = sb + SB_QL + (uint32_t)dc * 16384;
#pragma unroll
            for (int ks = 0; ks < 4; ++ks) {
                const int rA = wid * 16 + (lane & 15);
                const uint32_t offA = (uint32_t)(rA * 128 +
                    ((ks * 32 + (lane >> 4) * 16) ^ ((rA & 7) * 16)));
                uint32_t ah[4], al2[4];
                ldmx4(ah, qbase + offA);
                ldmx4(al2, qlbase + offA);
#pragma unroll
                for (int np = 0; np < 8; ++np) {
                    const int rB = np * 16 + ((lane >> 4) << 3) + (lane & 7);
                    const uint32_t offB = (uint32_t)(rB * 128 +
                        ((ks * 32 + ((lane >> 3) & 1) * 16) ^ ((rB & 7) * 16)));
                    uint32_t bh4[4];
                    ldmx4(bh4, kbase + offB);
                    mma16816h(sacc[np * 2], ah, bh4[0], bh4[1]);
                    mma16816h(sacc[np * 2], al2, bh4[0], bh4[1]);
                    mma16816h(sacc[np * 2 + 1], ah, bh4[2], bh4[3]);
                    mma16816h(sacc[np * 2 + 1], al2, bh4[2], bh4[3]);
                }
            }
            ++t;
        }

        // --- online softmax in exp2 domain (S pre-scaled via Q) ---
        float mx0 = -1e30f, mx1 = -1e30f;
#pragma unroll
        for (int ni = 0; ni < 16; ++ni) {
            mx0 = fmaxf(mx0, fmaxf(sacc[ni][0], sacc[ni][1]));
            mx1 = fmaxf(mx1, fmaxf(sacc[ni][2], sacc[ni][3]));
        }
        mx0 = fmaxf(mx0, __shfl_xor_sync(0xffffffffu, mx0, 1));
        mx0 = fmaxf(mx0, __shfl_xor_sync(0xffffffffu, mx0, 2));
        mx1 = fmaxf(mx1, __shfl_xor_sync(0xffffffffu, mx1, 1));
        mx1 = fmaxf(mx1, __shfl_xor_sync(0xffffffffu, mx1, 2));
        const float mn0 = fmaxf(mrow0, mx0), mn1 = fmaxf(mrow1, mx1);
        const float cr0 = ex2_mufu(mrow0 - mn0), cr1 = ex2_mufu(mrow1 - mn1);
        mrow0 = mn0; mrow1 = mn1;
        float ps0 = 0.0f, ps1 = 0.0f;
#pragma unroll
        for (int ni = 0; ni < 16; ++ni) {
            sacc[ni][0] = ex2_mufu(sacc[ni][0] - mn0);    // MUFU pipe
            sacc[ni][1] = exp2_poly(sacc[ni][1] - mn0);   // FMA pipe
            sacc[ni][2] = ex2_mufu(sacc[ni][2] - mn1);
            sacc[ni][3] = exp2_poly(sacc[ni][3] - mn1);
            ps0 += sacc[ni][0] + sacc[ni][1];
            ps1 += sacc[ni][2] + sacc[ni][3];
        }
        ps0 += __shfl_xor_sync(0xffffffffu, ps0, 1);
        ps0 += __shfl_xor_sync(0xffffffffu, ps0, 2);
        ps1 += __shfl_xor_sync(0xffffffffu, ps1, 1);
        ps1 += __shfl_xor_sync(0xffffffffu, ps1, 2);
        lsum0 = lsum0 * cr0 + ps0;
        lsum1 = lsum1 * cr1 + ps1;
#pragma unroll
        for (int ni = 0; ni < 16; ++ni) {
            o_acc[ni][0] *= cr0; o_acc[ni][1] *= cr0;
            o_acc[ni][2] *= cr1; o_acc[ni][3] *= cr1;
        }

        // --- O += P@Vh + P@Vl  (P single fp16 from S accumulators) ---
#pragma unroll 1
        for (int ki = 0; ki < 8; ++ki) {
            uint32_t aph[4];
#pragma unroll
            for (int half = 0; half < 2; ++half) {
                const float* p = sacc[2 * ki + half];
                aph[half * 2 + 0] = pack_f16x2(p[0], p[1]);
                aph[half * 2 + 1] = pack_f16x2(p[2], p[3]);
            }
#pragma unroll
            for (int np = 0; np < 8; ++np) {
                const int rB = np * 16 + ((lane >> 4) << 3) + (lane & 7);
                const uint32_t offB = (uint32_t)(rB * 256 +
                    ((ki * 32 + ((lane >> 3) & 1) * 16) ^ ((rB & 7) * 16)));
                uint32_t vh4[4], vl4[4];
                ldmx4(vh4, sb + SB_VTH + offB);
                ldmx4(vl4, sb + SB_VTL + offB);
                mma16816h(o_acc[np * 2], aph, vh4[0], vh4[1]);
                mma16816h(o_acc[np * 2], aph, vl4[0], vl4[1]);
                mma16816h(o_acc[np * 2 + 1], aph, vh4[2], vh4[3]);
                mma16816h(o_acc[np * 2 + 1], aph, vl4[2], vl4[3]);
            }
        }
    }

    // --- epilogue: normalize, bf16 trunc-split hi/lo, write (B,M,2048) ---
    const float inv0 = 1.0f / lsum0, inv1 = 1.0f / lsum1;
    const int b = bh >> 4, h = bh & 15;
    const int g = lane >> 2, t2 = lane & 3;
    const int mrow = m0 + wid * 16 + g;
#pragma unroll
    for (int ni = 0; ni < 16; ++ni) {
        const int col = h * DHh + ni * 8 + t2 * 2;
        const float y0 = o_acc[ni][0] * inv0, y1 = o_acc[ni][1] * inv0;
        const float z0 = o_acc[ni][2] * inv1, z1 = o_acc[ni][3] * inv1;
        const size_t i0 = ((size_t)(b * Mm + mrow)) * Dd + col;
        const size_t i1 = ((size_t)(b * Mm + mrow + 8)) * Dd + col;
        *(uint32_t*)(Oh + i0) = prmt_hi(__float_as_uint(y0), __float_as_uint(y1));
        *(uint32_t*)(Ol + i0) = cvt_bf16x2_pair(y0 - trunc_bf(y0), y1 - trunc_bf(y1));
        *(uint32_t*)(Oh + i1) = prmt_hi(__float_as_uint(z0), __float_as_uint(z1));
        *(uint32_t*)(Ol + i1) = cvt_bf16x2_pair(z0 - trunc_bf(z0), z1 - trunc_bf(z1));
    }
}

// ---------------------------------------------------------------------------
extern "C" void kernel_launch(void* const* d_in, const int* in_sizes, int n_in,
                              void* d_out, int out_size) {
    (void)in_sizes; (void)n_in; (void)out_size;
    const float* query = (const float*)d_in[0];
    const float* kv    = (const float*)d_in[1];
    const float* W_QC  = (const float*)d_in[2];
    const float* W_KC  = (const float*)d_in[3];
    const float* W_QR  = (const float*)d_in[4];
    const float* W_KR  = (const float*)d_in[5];
    const float* W_V   = (const float*)d_in[6];
    const float* W_O   = (const float*)d_in[7];
    float* out = (float*)d_out;

    __nv_bfloat16 *qh, *ql, *kvh, *kvl, *obh, *obl;
    __nv_bfloat16 *wqch, *wqcl, *wkch, *wkcl, *wvh, *wvl, *woh, *wol;
    __nv_bfloat16 *wqrh, *wqrl, *wkrh, *wkrl;
    __half *Qhp, *Qlp, *Khp, *Vthp, *Vtlp;
    cudaGetSymbolAddress((void**)&qh, g_qh);   cudaGetSymbolAddress((void**)&ql, g_ql);
    cudaGetSymbolAddress((void**)&kvh, g_kvh); cudaGetSymbolAddress((void**)&kvl, g_kvl);
    cudaGetSymbolAddress((void**)&obh, g_obh); cudaGetSymbolAddress((void**)&obl, g_obl);
    cudaGetSymbolAddress((void**)&wqch, g_wqch); cudaGetSymbolAddress((void**)&wqcl, g_wqcl);
    cudaGetSymbolAddress((void**)&wkch, g_wkch); cudaGetSymbolAddress((void**)&wkcl, g_wkcl);
    cudaGetSymbolAddress((void**)&wvh, g_wvh);   cudaGetSymbolAddress((void**)&wvl, g_wvl);
    cudaGetSymbolAddress((void**)&woh, g_woh);   cudaGetSymbolAddress((void**)&wol, g_wol);
    cudaGetSymbolAddress((void**)&wqrh, g_wqrh); cudaGetSymbolAddress((void**)&wqrl, g_wqrl);
    cudaGetSymbolAddress((void**)&wkrh, g_wkrh); cudaGetSymbolAddress((void**)&wkrl, g_wkrl);
    cudaGetSymbolAddress((void**)&Qhp, g_Qh);   cudaGetSymbolAddress((void**)&Qlp, g_Ql);
    cudaGetSymbolAddress((void**)&Khp, g_Kh);
    cudaGetSymbolAddress((void**)&Vthp, g_Vth); cudaGetSymbolAddress((void**)&Vtlp, g_Vtl);

    const int GEMM_SMEM = 196608;  // 3 stages x 64KB
    cudaFuncSetAttribute(hmma_gemm<0>, cudaFuncAttributeMaxDynamicSharedMemorySize, GEMM_SMEM);
    cudaFuncSetAttribute(hmma_gemm<1>, cudaFuncAttributeMaxDynamicSharedMemorySize, GEMM_SMEM);
    cudaFuncSetAttribute(hmma_gemm<2>, cudaFuncAttributeMaxDynamicSharedMemorySize, GEMM_SMEM);
    cudaFuncSetAttribute(hmma_gemm<3>, cudaFuncAttributeMaxDynamicSharedMemorySize, GEMM_SMEM);
    cudaFuncSetAttribute(flash_hmma, cudaFuncAttributeMaxDynamicSharedMemorySize, FA_SMEM);

    rope_table_kernel<<<Mm, 32>>>();
    cvt_split<<<(int)(SZ_X / 1024), 256>>>((const float4*)query, (uint2*)qh, (uint2*)ql, (int)(SZ_X / 4));
    cvt_split<<<(int)(SZ_X / 1024), 256>>>((const float4*)kv, (uint2*)kvh, (uint2*)kvl, (int)(SZ_X / 4));
    cvt_split<<<(int)(SZ_W2 / 1024), 256>>>((const float4*)W_QC, (uint2*)wqch, (uint2*)wqcl, (int)(SZ_W2 / 4));
    cvt_split<<<(int)(SZ_W2 / 1024), 256>>>((const float4*)W_KC, (uint2*)wkch, (uint2*)wkcl, (int)(SZ_W2 / 4));
    cvt_split<<<(int)(SZ_W1 / 1024), 256>>>((const float4*)W_QR, (uint2*)wqrh, (uint2*)wqrl, (int)(SZ_W1 / 4));
    cvt_split<<<(int)(SZ_W1 / 1024), 256>>>((const float4*)W_KR, (uint2*)wkrh, (uint2*)wkrl, (int)(SZ_W1 / 4));
    cvt_split<<<(int)(SZ_W2 / 1024), 256>>>((const float4*)W_V, (uint2*)wvh, (uint2*)wvl, (int)(SZ_W2 / 4));
    cvt_split<<<(int)(SZ_W2 / 1024), 256>>>((const float4*)W_O, (uint2*)woh, (uint2*)wol, (int)(SZ_W2 / 4));

    // Projections (bf16x3): Q -> fp16 hi/lo (pre-scaled); K -> fp16 single; V -> fp16 hi/lo
    hmma_gemm<1><<<dim3(16, 32), 256, GEMM_SMEM>>>(qh, ql, wqch, wqcl, nullptr, Qhp, Qlp, SCALE2);
    hmma_gemm<2><<<dim3(8, 32), 256, GEMM_SMEM>>>(qh, ql, wqrh, wqrl, nullptr, Qhp, Qlp, SCALE2);
    hmma_gemm<1><<<dim3(16, 32), 256, GEMM_SMEM>>>(kvh, kvl, wkch, wkcl, nullptr, Khp, nullptr, 1.0f);
    hmma_gemm<2><<<dim3(8, 32), 256, GEMM_SMEM>>>(kvh, kvl, wkrh, wkrl, nullptr, Khp, nullptr, 1.0f);
    hmma_gemm<3><<<dim3(16, 32), 256, GEMM_SMEM>>>(kvh, kvl, wvh, wvl, nullptr, Vthp, Vtlp, 1.0f);

    flash_hmma<<<dim3(16, 32), 256, FA_SMEM>>>(Qhp, Qlp, Khp, Vthp, Vtlp, obh, obl);

    hmma_gemm<0><<<dim3(16, 32), 256, GEMM_SMEM>>>(obh, obl, woh, wol, out, nullptr, nullptr, 1.0f);
}

// round 16
// speedup vs baseline: 3.1662x; 1.1639x over previous
#include <cuda_runtime.h>
#include <cuda_bf16.h>
#include <cuda_fp16.h>
#include <math.h>
#include <stdint.h>

// Problem constants
#define Bb   2
#define Mm   2048
#define Dd   2048
#define Hh   16
#define DHh  128
#define DRr  64
#define DQq  192   // concatenated head dim: 128 (C path) + 64 (RoPE path)

// 1/sqrt(192) * log2(e): Q is pre-scaled so S is in exp2 domain
#define SCALE2 0.10411755f

__device__ float g_cos[Mm * DRr];
__device__ float g_sin[Mm * DRr];

#define SZ_X  ((size_t)Bb * Mm * Dd)        // 8388608
#define SZ_W2 ((size_t)2048 * 2048)
#define SZ_W1 ((size_t)1024 * 2048)
#define SZ_QK ((size_t)Bb * Hh * Mm * DQq)  // 12582912
#define SZ_V  ((size_t)Bb * Hh * DHh * Mm)  // 8388608
// activations: fp16 hi/lo (exact split); weights: single fp16
__device__ __half g_qh[SZ_X],  g_ql[SZ_X];
__device__ __half g_kvh[SZ_X], g_kvl[SZ_X];
__device__ __half g_obh[SZ_X], g_obl[SZ_X];
__device__ __half g_wqc[SZ_W2], g_wkc[SZ_W2], g_wv[SZ_W2], g_wo[SZ_W2];
__device__ __half g_wqr[SZ_W1], g_wkr[SZ_W1];
// attention operands (fp16, written by projection epilogues)
__device__ __half g_Qh[SZ_QK], g_Ql[SZ_QK];  // (B,H,M,192) pre-scaled, hi+lo
__device__ __half g_Kh[SZ_QK];               // (B,H,N,192) single fp16
__device__ __half g_Vth[SZ_V], g_Vtl[SZ_V];  // (B,H,128d,2048s) transposed hi+lo

// ---------------------------------------------------------------------------
// Helpers (generic sm_80/90 features only — target is sm_103 non-'a')
// ---------------------------------------------------------------------------
__device__ __forceinline__ uint32_t smem_u32(const void* p) {
    uint32_t a;
    asm("{ .reg .u64 t; cvta.to.shared.u64 t, %1; cvt.u32.u64 %0, t; }"
        : "=r"(a) : "l"(p));
    return a;
}
__device__ __forceinline__ void cp16(uint32_t s, const void* g) {
    asm volatile("cp.async.cg.shared.global [%0], [%1], 16;" :: "r"(s), "l"(g));
}
#define CP_COMMIT() asm volatile("cp.async.commit_group;" ::: "memory")
#define CP_WAIT0()  asm volatile("cp.async.wait_group 0;" ::: "memory")
#define CP_WAIT1()  asm volatile("cp.async.wait_group 1;" ::: "memory")

__device__ __forceinline__ void ldmx4(uint32_t r[4], uint32_t a) {
    asm volatile("ldmatrix.sync.aligned.m8n8.x4.shared.b16 {%0,%1,%2,%3}, [%4];"
                 : "=r"(r[0]), "=r"(r[1]), "=r"(r[2]), "=r"(r[3]) : "r"(a));
}
__device__ __forceinline__ void mma16816h(float c[4], const uint32_t a[4],
                                          uint32_t b0, uint32_t b1) {
    asm volatile(
        "mma.sync.aligned.m16n8k16.row.col.f32.f16.f16.f32 "
        "{%0,%1,%2,%3}, {%4,%5,%6,%7}, {%8,%9}, {%0,%1,%2,%3};"
        : "+f"(c[0]), "+f"(c[1]), "+f"(c[2]), "+f"(c[3])
        : "r"(a[0]), "r"(a[1]), "r"(a[2]), "r"(a[3]), "r"(b0), "r"(b1));
}
// MUFU exp2 (ex2.approx.f32)
__device__ __forceinline__ float ex2_mufu(float x) {
    float r;
    asm("ex2.approx.f32 %0, %1;" : "=f"(r) : "f"(x));
    return r;
}
// fp16 pack: x -> low half, y -> high half
__device__ __forceinline__ uint32_t pack_f16x2(float x, float y) {
    __half2 h = __float22half2_rn(make_float2(x, y));
    return *reinterpret_cast<uint32_t*>(&h);
}
// FMA-pipe exp2 (magic-number round + deg-4 Taylor), rel err ~4e-5, t in [-100, 0]
__device__ __forceinline__ float exp2_poly(float t) {
    t = fmaxf(t, -100.0f);
    float z = __fadd_rn(t, 12582912.0f);
    float n = __fsub_rn(z, 12582912.0f);
    float f = t - n;
    float p = fmaf(f, 0.0096181291f, 0.0555041087f);
    p = fmaf(f, p, 0.2402265069f);
    p = fmaf(f, p, 0.6931471806f);
    p = fmaf(f, p, 1.0f);
    uint32_t sc = (__float_as_uint(z) + (127u - 4194304u)) << 23;
    return p * __uint_as_float(sc);
}

// ---------------------------------------------------------------------------
// fp32 -> fp16 hi/lo split (activations): hi = rn(x); lo = rn(x - hi)
// ---------------------------------------------------------------------------
__global__ void __launch_bounds__(256)
cvt_split_f16(const float4* __restrict__ src, uint2* __restrict__ hi,
              uint2* __restrict__ lo, int n4) {
    int i = blockIdx.x * 256 + threadIdx.x;
    if (i >= n4) return;
    float4 v = src[i];
    __half2 h01 = __float22half2_rn(make_float2(v.x, v.y));
    __half2 h23 = __float22half2_rn(make_float2(v.z, v.w));
    hi[i] = make_uint2(*reinterpret_cast<uint32_t*>(&h01),
                       *reinterpret_cast<uint32_t*>(&h23));
    float2 f01 = __half22float2(h01), f23 = __half22float2(h23);
    lo[i] = make_uint2(pack_f16x2(v.x - f01.x, v.y - f01.y),
                       pack_f16x2(v.z - f23.x, v.w - f23.y));
}
// fp32 -> single fp16 (weights)
__global__ void __launch_bounds__(256)
cvt_f16(const float4* __restrict__ src, uint2* __restrict__ dst, int n4) {
    int i = blockIdx.x * 256 + threadIdx.x;
    if (i >= n4) return;
    float4 v = src[i];
    dst[i] = make_uint2(pack_f16x2(v.x, v.y), pack_f16x2(v.z, v.w));
}

// ---------------------------------------------------------------------------
// RoPE table (fp64 angles)
// ---------------------------------------------------------------------------
__global__ void rope_table_kernel() {
    int s = blockIdx.x;
    int i = threadIdx.x;  // 0..31
    double freq = exp(-((double)(2 * i) / 64.0) * log(1000000.0));
    double ang = (double)s * freq;
    float c = (float)cos(ang);
    float sn = (float)sin(ang);
    g_cos[s * 64 + 2 * i] = c;  g_cos[s * 64 + 2 * i + 1] = c;
    g_sin[s * 64 + 2 * i] = sn; g_sin[s * 64 + 2 * i + 1] = sn;
}

// ---------------------------------------------------------------------------
// HMMA fp16x2 NT GEMM: S = Ah*B + Al*B (A hi/lo fp16, B single fp16).
// 3-stage cp.async pipeline; SMEM/stage: Ah 16K + Al 16K + B 16K = 48KB.
// MODE 0: fp32 plain (ldc=2048)
// MODE 1: -> fp16 (B,H,S,192)[0:128]; ol!=null => hi/lo split (Q), else single (K)
// MODE 2: RoPE -> fp16 (B,H,S,192)[128:192]; same hi/lo rule
// MODE 3: V -> fp16 hi/lo transposed (B,H,128,2048)
// ---------------------------------------------------------------------------
#define GSTG 49152
__device__ __forceinline__ void load_chunk(uint32_t sb, int tid, int row0, int col0,
        const __half* Ah, const __half* Al, const __half* B, int c, int stage) {
    const size_t k0b = (size_t)c * 128;
    const uint32_t base = sb + (uint32_t)stage * GSTG;
#pragma unroll
    for (int i = 0; i < 4; ++i) {
        int flat = tid + i * 256;
        int row = flat >> 3;
        int cb = (flat & 7) << 4;
        uint32_t so = (uint32_t)(row * 128 + (cb ^ ((row & 7) * 16)));
        const size_t ra = ((size_t)(row0 + row) * Dd) * 2 + k0b + cb;
        const size_t rb = ((size_t)(col0 + row) * Dd) * 2 + k0b + cb;
        cp16(base + so,         (const char*)Ah + ra);
        cp16(base + 16384 + so, (const char*)Al + ra);
        cp16(base + 32768 + so, (const char*)B + rb);
    }
}

template <int MODE>
__global__ void __launch_bounds__(256, 1)
hmma_gemm(const __half* __restrict__ Ah, const __half* __restrict__ Al,
          const __half* __restrict__ B,
          float* __restrict__ outf,
          __half* __restrict__ oh, __half* __restrict__ ol,
          float oscale) {
    extern __shared__ __align__(1024) char smem[];
    const uint32_t sb = smem_u32(smem);
    const int tid = threadIdx.x;
    const int wid = tid >> 5, lane = tid & 31;
    const int wm = wid >> 2, wn = wid & 3;
    const int row0 = blockIdx.y * 128, col0 = blockIdx.x * 128;

    float acc[4][4][4];
#pragma unroll
    for (int mi = 0; mi < 4; ++mi)
#pragma unroll
        for (int ni = 0; ni < 4; ++ni)
#pragma unroll
            for (int k = 0; k < 4; ++k) acc[mi][ni][k] = 0.0f;

    const int aRow = wm * 64 + (lane & 15);
    const int aKs  = (lane >> 4) * 16;
    const int bRow = wn * 32 + ((lane >> 4) << 3) + (lane & 7);
    const int bKs  = ((lane >> 3) & 1) * 16;

    load_chunk(sb, tid, row0, col0, Ah, Al, B, 0, 0);
    CP_COMMIT();
    load_chunk(sb, tid, row0, col0, Ah, Al, B, 1, 1);
    CP_COMMIT();

    int st = 0;
    for (int c = 0; c < 32; ++c) {
        CP_WAIT1();
        __syncthreads();
        if (c + 2 < 32) {
            int st2 = st + 2; if (st2 >= 3) st2 -= 3;
            load_chunk(sb, tid, row0, col0, Ah, Al, B, c + 2, st2);
            CP_COMMIT();
        }
        const uint32_t base = sb + (uint32_t)st * GSTG;
#pragma unroll
        for (int ks = 0; ks < 4; ++ks) {
            const int kA = ks * 32 + aKs;
            const int kB = ks * 32 + bKs;
            uint32_t ah[4][4], al[4][4];
#pragma unroll
            for (int mi = 0; mi < 4; ++mi) {
                const int r = aRow + mi * 16;
                const uint32_t off = (uint32_t)(r * 128 + (kA ^ ((r & 7) * 16)));
                ldmx4(ah[mi], base + off);
                ldmx4(al[mi], base + 16384 + off);
            }
            uint32_t bh[2][4];
#pragma unroll
            for (int np = 0; np < 2; ++np) {
                const int r = bRow + np * 16;
                const uint32_t off = (uint32_t)(r * 128 + (kB ^ ((r & 7) * 16)));
                ldmx4(bh[np], base + 32768 + off);
            }
#pragma unroll
            for (int mi = 0; mi < 4; ++mi)
#pragma unroll
                for (int ni = 0; ni < 4; ++ni) {
                    const uint32_t* ph = &bh[ni >> 1][(ni & 1) * 2];
                    mma16816h(acc[mi][ni], ah[mi], ph[0], ph[1]);
                    mma16816h(acc[mi][ni], al[mi], ph[0], ph[1]);
                }
        }
        st = (st == 2) ? 0 : st + 1;
    }

#pragma unroll
    for (int mi = 0; mi < 4; ++mi)
#pragma unroll
        for (int ni = 0; ni < 4; ++ni)
#pragma unroll
            for (int h2 = 0; h2 < 2; ++h2) {
                const int row = row0 + wm * 64 + mi * 16 + (lane >> 2) + h2 * 8;
                const int col = col0 + wn * 32 + ni * 8 + (lane & 3) * 2;
                const float v0 = acc[mi][ni][h2 * 2 + 0];
                const float v1 = acc[mi][ni][h2 * 2 + 1];
                const int b = row >> 11;
                const int ss = row & 2047;
                if (MODE == 0) {
                    *(float2*)(outf + (size_t)row * Dd + col) = make_float2(v0, v1);
                } else if (MODE == 1 || MODE == 2) {
                    float y0, y1;
                    size_t idx;
                    if (MODE == 1) {
                        y0 = v0 * oscale; y1 = v1 * oscale;
                        const int hH = col >> 7, jj = col & 127;
                        idx = (((size_t)(b * Hh + hH) * Mm) + ss) * DQq + jj;
                    } else {
                        const int hH = col >> 6, jr = col & 63;
                        const float cv = g_cos[ss * 64 + jr];
                        const float sv = g_sin[ss * 64 + jr];
                        y0 = (v0 * cv - v1 * sv) * oscale;
                        y1 = (v1 * cv + v0 * sv) * oscale;
                        idx = (((size_t)(b * Hh + hH) * Mm) + ss) * DQq + 128 + jr;
                    }
                    __half2 hh = __float22half2_rn(make_float2(y0, y1));
                    *(__half2*)(oh + idx) = hh;
                    if (ol) {
                        float2 hf = __half22float2(hh);
                        *(uint32_t*)(ol + idx) = pack_f16x2(y0 - hf.x, y1 - hf.y);
                    }
                } else {  // MODE 3: V transposed (B,H,128,2048), fp16 hi/lo
                    const int hH = col >> 7, jj = col & 127;
                    const size_t idx = (((size_t)(b * Hh + hH) * DHh) + jj) * Mm + ss;
                    __half h0 = __float2half_rn(v0);
                    oh[idx] = h0;
                    ol[idx] = __float2half_rn(v0 - __half2float(h0));
                    __half h1 = __float2half_rn(v1);
                    oh[idx + Mm] = h1;
                    ol[idx + Mm] = __float2half_rn(v1 - __half2float(h1));
                }
            }
}

// ---------------------------------------------------------------------------
// Flash attention, fp16 two-term HMMA (unchanged from R13 except fp16 output).
// SMEM: Qh/Ql resident 3x[128x64] (96KB) + K 2-stage 16KB x2 (32KB)
//       + V^T [128x128] hi/lo (64KB) = 192KB.
// ---------------------------------------------------------------------------
#define SB_QL   49152
#define SB_K    98304
#define SB_VTH  131072
#define SB_VTL  163840
#define FA_SMEM 196608

__device__ __forceinline__ void ld_tile128(uint32_t dst, int tid,
        const __half* src, int lds) {
#pragma unroll
    for (int i = 0; i < 4; ++i) {
        int flat = tid + i * 256;
        int row = flat >> 3;
        int cb = (flat & 7) << 4;
        uint32_t so = (uint32_t)(row * 128 + (cb ^ ((row & 7) * 16)));
        cp16(dst + so, (const char*)src + (size_t)row * lds * 2 + cb);
    }
}
__device__ __forceinline__ void ld_tile256(uint32_t dst, int tid,
        const __half* src, int lds) {
#pragma unroll
    for (int i = 0; i < 8; ++i) {
        int flat = tid + i * 256;
        int row = flat >> 4;
        int cb = (flat & 15) << 4;
        uint32_t so = (uint32_t)(row * 256 + (cb ^ ((row & 7) * 16)));
        cp16(dst + so, (const char*)src + (size_t)row * lds * 2 + cb);
    }
}

__global__ void __launch_bounds__(256, 1)
flash_hmma(const __half* __restrict__ Qh, const __half* __restrict__ Ql,
           const __half* __restrict__ Kh,
           const __half* __restrict__ Vth, const __half* __restrict__ Vtl,
           __half* __restrict__ Oh, __half* __restrict__ Ol) {
    extern __shared__ __align__(1024) char smem[];
    const uint32_t sb = smem_u32(smem);
    const int tid = threadIdx.x;
    const int wid = tid >> 5, lane = tid & 31;
    const int bh = blockIdx.y;
    const int m0 = blockIdx.x * 128;

    const __half* Qhb = Qh + ((size_t)bh * Mm + m0) * DQq;
    const __half* Qlb = Ql + ((size_t)bh * Mm + m0) * DQq;
    const __half* Khb = Kh + (size_t)bh * Mm * DQq;
    const __half* Vhb = Vth + (size_t)bh * DHh * Mm;
    const __half* Vlb = Vtl + (size_t)bh * DHh * Mm;

    float o_acc[16][4];
#pragma unroll
    for (int ni = 0; ni < 16; ++ni)
#pragma unroll
        for (int k = 0; k < 4; ++k) o_acc[ni][k] = 0.0f;
    float mrow0 = -1e30f, mrow1 = -1e30f, lsum0 = 0.0f, lsum1 = 0.0f;

    // prologue: resident Q (3 chunks hi+lo) + K chunk 0
#pragma unroll
    for (int dc = 0; dc < 3; ++dc) {
        ld_tile128(sb + dc * 16384, tid, Qhb + dc * 64, DQq);
        ld_tile128(sb + SB_QL + dc * 16384, tid, Qlb + dc * 64, DQq);
    }
    ld_tile128(sb + SB_K, tid, Khb, DQq);
    CP_COMMIT();

    int t = 0;
#pragma unroll 1
    for (int n0i = 0; n0i < 16; ++n0i) {
        float sacc[16][4];
#pragma unroll
        for (int ni = 0; ni < 16; ++ni)
#pragma unroll
            for (int k = 0; k < 4; ++k) sacc[ni][k] = 0.0f;

#pragma unroll 1
        for (int dc = 0; dc < 3; ++dc) {
            CP_WAIT0();
            __syncthreads();
            if (t + 1 < 48) {
                const int nn = (t + 1) / 3, ndc = (t + 1) % 3;
                const uint32_t kst = SB_K + (uint32_t)((t + 1) & 1) * 16384;
                ld_tile128(sb + kst, tid, Khb + (size_t)(nn * 128) * DQq + ndc * 64, DQq);
                if (ndc == 2) {
                    ld_tile256(sb + SB_VTH, tid, Vhb + nn * 128, Mm);
                    ld_tile256(sb + SB_VTL, tid, Vlb + nn * 128, Mm);
                }
                CP_COMMIT();
            }
            // S += Qh@K^T + Ql@K^T   (fp16 x2)
            const uint32_t kbase = sb + SB_K + (uint32_t)(t & 1) * 16384;
            const uint32_t qbase = sb + (uint32_t)dc * 16384;
            const uint32_t qlbase = sb + SB_QL + (uint32_t)dc * 16384;
#pragma unroll
            for (int ks = 0; ks < 4; ++ks) {
                const int rA = wid * 16 + (lane & 15);
                const uint32_t offA = (uint32_t)(rA * 128 +
                    ((ks * 32 + (lane >> 4) * 16) ^ ((rA & 7) * 16)));
                uint32_t ah[4], al2[4];
                ldmx4(ah, qbase + offA);
                ldmx4(al2, qlbase + offA);
#pragma unroll
                for (int np = 0; np < 8; ++np) {
                    const int rB = np * 16 + ((lane >> 4) << 3) + (lane & 7);
                    const uint32_t offB = (uint32_t)(rB * 128 +
                        ((ks * 32 + ((lane >> 3) & 1) * 16) ^ ((rB & 7) * 16)));
                    uint32_t bh4[4];
                    ldmx4(bh4, kbase + offB);
                    mma16816h(sacc[np * 2], ah, bh4[0], bh4[1]);
                    mma16816h(sacc[np * 2], al2, bh4[0], bh4[1]);
                    mma16816h(sacc[np * 2 + 1], ah, bh4[2], bh4[3]);
                    mma16816h(sacc[np * 2 + 1], al2, bh4[2], bh4[3]);
                }
            }
            ++t;
        }

        // --- online softmax in exp2 domain (S pre-scaled via Q) ---
        float mx0 = -1e30f, mx1 = -1e30f;
#pragma unroll
        for (int ni = 0; ni < 16; ++ni) {
            mx0 = fmaxf(mx0, fmaxf(sacc[ni][0], sacc[ni][1]));
            mx1 = fmaxf(mx1, fmaxf(sacc[ni][2], sacc[ni][3]));
        }
        mx0 = fmaxf(mx0, __shfl_xor_sync(0xffffffffu, mx0, 1));
        mx0 = fmaxf(mx0, __shfl_xor_sync(0xffffffffu, mx0, 2));
        mx1 = fmaxf(mx1, __shfl_xor_sync(0xffffffffu, mx1, 1));
        mx1 = fmaxf(mx1, __shfl_xor_sync(0xffffffffu, mx1, 2));
        const float mn0 = fmaxf(mrow0, mx0), mn1 = fmaxf(mrow1, mx1);
        const float cr0 = ex2_mufu(mrow0 - mn0), cr1 = ex2_mufu(mrow1 - mn1);
        mrow0 = mn0; mrow1 = mn1;
        float ps0 = 0.0f, ps1 = 0.0f;
#pragma unroll
        for (int ni = 0; ni < 16; ++ni) {
            sacc[ni][0] = ex2_mufu(sacc[ni][0] - mn0);    // MUFU pipe
            sacc[ni][1] = exp2_poly(sacc[ni][1] - mn0);   // FMA pipe
            sacc[ni][2] = ex2_mufu(sacc[ni][2] - mn1);
            sacc[ni][3] = exp2_poly(sacc[ni][3] - mn1);
            ps0 += sacc[ni][0] + sacc[ni][1];
            ps1 += sacc[ni][2] + sacc[ni][3];
        }
        ps0 += __shfl_xor_sync(0xffffffffu, ps0, 1);
        ps0 += __shfl_xor_sync(0xffffffffu, ps0, 2);
        ps1 += __shfl_xor_sync(0xffffffffu, ps1, 1);
        ps1 += __shfl_xor_sync(0xffffffffu, ps1, 2);
        lsum0 = lsum0 * cr0 + ps0;
        lsum1 = lsum1 * cr1 + ps1;
#pragma unroll
        for (int ni = 0; ni < 16; ++ni) {
            o_acc[ni][0] *= cr0; o_acc[ni][1] *= cr0;
            o_acc[ni][2] *= cr1; o_acc[ni][3] *= cr1;
        }

        // --- O += P@Vh + P@Vl  (P single fp16 from S accumulators) ---
#pragma unroll 1
        for (int ki = 0; ki < 8; ++ki) {
            uint32_t aph[4];
#pragma unroll
            for (int half = 0; half < 2; ++half) {
                const float* p = sacc[2 * ki + half];
                aph[half * 2 + 0] = pack_f16x2(p[0], p[1]);
                aph[half * 2 + 1] = pack_f16x2(p[2], p[3]);
            }
#pragma unroll
            for (int np = 0; np < 8; ++np) {
                const int rB = np * 16 + ((lane >> 4) << 3) + (lane & 7);
                const uint32_t offB = (uint32_t)(rB * 256 +
                    ((ki * 32 + ((lane >> 3) & 1) * 16) ^ ((rB & 7) * 16)));
                uint32_t vh4[4], vl4[4];
                ldmx4(vh4, sb + SB_VTH + offB);
                ldmx4(vl4, sb + SB_VTL + offB);
                mma16816h(o_acc[np * 2], aph, vh4[0], vh4[1]);
                mma16816h(o_acc[np * 2], aph, vl4[0], vl4[1]);
                mma16816h(o_acc[np * 2 + 1], aph, vh4[2], vh4[3]);
                mma16816h(o_acc[np * 2 + 1], aph, vl4[2], vl4[3]);
            }
        }
    }

    // --- epilogue: normalize, fp16 hi/lo split, write (B,M,2048) ---
    const float inv0 = 1.0f / lsum0, inv1 = 1.0f / lsum1;
    const int b = bh >> 4, h = bh & 15;
    const int g = lane >> 2, t2 = lane & 3;
    const int mrow = m0 + wid * 16 + g;
#pragma unroll
    for (int ni = 0; ni < 16; ++ni) {
        const int col = h * DHh + ni * 8 + t2 * 2;
        const float y0 = o_acc[ni][0] * inv0, y1 = o_acc[ni][1] * inv0;
        const float z0 = o_acc[ni][2] * inv1, z1 = o_acc[ni][3] * inv1;
        const size_t i0 = ((size_t)(b * Mm + mrow)) * Dd + col;
        const size_t i1 = ((size_t)(b * Mm + mrow + 8)) * Dd + col;
        __half2 hy = __float22half2_rn(make_float2(y0, y1));
        __half2 hz = __float22half2_rn(make_float2(z0, z1));
        *(__half2*)(Oh + i0) = hy;
        *(__half2*)(Oh + i1) = hz;
        float2 fy = __half22float2(hy), fz = __half22float2(hz);
        *(uint32_t*)(Ol + i0) = pack_f16x2(y0 - fy.x, y1 - fy.y);
        *(uint32_t*)(Ol + i1) = pack_f16x2(z0 - fz.x, z1 - fz.y);
    }
}

// ---------------------------------------------------------------------------
extern "C" void kernel_launch(void* const* d_in, const int* in_sizes, int n_in,
                              void* d_out, int out_size) {
    (void)in_sizes; (void)n_in; (void)out_size;
    const float* query = (const float*)d_in[0];
    const float* kv    = (const float*)d_in[1];
    const float* W_QC  = (const float*)d_in[2];
    const float* W_KC  = (const float*)d_in[3];
    const float* W_QR  = (const float*)d_in[4];
    const float* W_KR  = (const float*)d_in[5];
    const float* W_V   = (const float*)d_in[6];
    const float* W_O   = (const float*)d_in[7];
    float* out = (float*)d_out;

    __half *qh, *ql, *kvh, *kvl, *obh, *obl;
    __half *wqc, *wkc, *wv, *wo, *wqr, *wkr;
    __half *Qhp, *Qlp, *Khp, *Vthp, *Vtlp;
    cudaGetSymbolAddress((void**)&qh, g_qh);   cudaGetSymbolAddress((void**)&ql, g_ql);
    cudaGetSymbolAddress((void**)&kvh, g_kvh); cudaGetSymbolAddress((void**)&kvl, g_kvl);
    cudaGetSymbolAddress((void**)&obh, g_obh); cudaGetSymbolAddress((void**)&obl, g_obl);
    cudaGetSymbolAddress((void**)&wqc, g_wqc); cudaGetSymbolAddress((void**)&wkc, g_wkc);
    cudaGetSymbolAddress((void**)&wv, g_wv);   cudaGetSymbolAddress((void**)&wo, g_wo);
    cudaGetSymbolAddress((void**)&wqr, g_wqr); cudaGetSymbolAddress((void**)&wkr, g_wkr);
    cudaGetSymbolAddress((void**)&Qhp, g_Qh);  cudaGetSymbolAddress((void**)&Qlp, g_Ql);
    cudaGetSymbolAddress((void**)&Khp, g_Kh);
    cudaGetSymbolAddress((void**)&Vthp, g_Vth); cudaGetSymbolAddress((void**)&Vtlp, g_Vtl);

    const int GEMM_SMEM = 3 * GSTG;  // 147456
    cudaFuncSetAttribute(hmma_gemm<0>, cudaFuncAttributeMaxDynamicSharedMemorySize, GEMM_SMEM);
    cudaFuncSetAttribute(hmma_gemm<1>, cudaFuncAttributeMaxDynamicSharedMemorySize, GEMM_SMEM);
    cudaFuncSetAttribute(hmma_gemm<2>, cudaFuncAttributeMaxDynamicSharedMemorySize, GEMM_SMEM);
    cudaFuncSetAttribute(hmma_gemm<3>, cudaFuncAttributeMaxDynamicSharedMemorySize, GEMM_SMEM);
    cudaFuncSetAttribute(flash_hmma, cudaFuncAttributeMaxDynamicSharedMemorySize, FA_SMEM);

    rope_table_kernel<<<Mm, 32>>>();
    cvt_split_f16<<<(int)(SZ_X / 1024), 256>>>((const float4*)query, (uint2*)qh, (uint2*)ql, (int)(SZ_X / 4));
    cvt_split_f16<<<(int)(SZ_X / 1024), 256>>>((const float4*)kv, (uint2*)kvh, (uint2*)kvl, (int)(SZ_X / 4));
    cvt_f16<<<(int)(SZ_W2 / 1024), 256>>>((const float4*)W_QC, (uint2*)wqc, (int)(SZ_W2 / 4));
    cvt_f16<<<(int)(SZ_W2 / 1024), 256>>>((const float4*)W_KC, (uint2*)wkc, (int)(SZ_W2 / 4));
    cvt_f16<<<(int)(SZ_W1 / 1024), 256>>>((const float4*)W_QR, (uint2*)wqr, (int)(SZ_W1 / 4));
    cvt_f16<<<(int)(SZ_W1 / 1024), 256>>>((const float4*)W_KR, (uint2*)wkr, (int)(SZ_W1 / 4));
    cvt_f16<<<(int)(SZ_W2 / 1024), 256>>>((const float4*)W_V, (uint2*)wv, (int)(SZ_W2 / 4));
    cvt_f16<<<(int)(SZ_W2 / 1024), 256>>>((const float4*)W_O, (uint2*)wo, (int)(SZ_W2 / 4));

    // Projections (fp16x2): Q -> fp16 hi/lo (pre-scaled); K -> fp16 single; V -> fp16 hi/lo
    hmma_gemm<1><<<dim3(16, 32), 256, GEMM_SMEM>>>(qh, ql, wqc, nullptr, Qhp, Qlp, SCALE2);
    hmma_gemm<2><<<dim3(8, 32), 256, GEMM_SMEM>>>(qh, ql, wqr, nullptr, Qhp, Qlp, SCALE2);
    hmma_gemm<1><<<dim3(16, 32), 256, GEMM_SMEM>>>(kvh, kvl, wkc, nullptr, Khp, nullptr, 1.0f);
    hmma_gemm<2><<<dim3(8, 32), 256, GEMM_SMEM>>>(kvh, kvl, wkr, nullptr, Khp, nullptr, 1.0f);
    hmma_gemm<3><<<dim3(16, 32), 256, GEMM_SMEM>>>(kvh, kvl, wv, nullptr, Vthp, Vtlp, 1.0f);

    flash_hmma<<<dim3(16, 32), 256, FA_SMEM>>>(Qhp, Qlp, Khp, Vthp, Vtlp, obh, obl);

    hmma_gemm<0><<<dim3(16, 32), 256, GEMM_SMEM>>>(obh, obl, wo, out, nullptr, nullptr, 1.0f);
}